// round 1
// baseline (speedup 1.0000x reference)
#include <cuda_runtime.h>
#include <cuda_bf16.h>

// Problem constants
#define NB 4
#define C  256
#define HR 60
#define WR 60
#define M  3600          // HR*WR
#define MP 3712          // padded to 29*128
#define GS 8
#define HH 480
#define WW 480

// GEMM tiling
#define BM 128
#define BN 128
#define BK 8
#define GB 29            // blocks per GEMM dim (29*128 = 3712)

#define NPOSB 1800       // pos-correction blocks: 14400 warps / 8 warps per block

// __device__ scratch (no allocation allowed)
__device__ float d_D1p[NB * C * MP];
__device__ float d_D2p[NB * C * MP];
__device__ float d_vm[NB * MP];
__device__ float d_partA[GB * GB * NB];
__device__ float d_partB[NPOSB];

// ---------------------------------------------------------------------------
// Zero-padded copies of desc1/desc2 so the GEMM has no bounds checks.
// ---------------------------------------------------------------------------
__global__ void pad_kernel(const float* __restrict__ d1, const float* __restrict__ d2) {
    int idx = blockIdx.x * blockDim.x + threadIdx.x;
    if (idx >= NB * C * MP) return;
    int mp = idx % MP;
    int nc = idx / MP;
    float v1 = 0.f, v2 = 0.f;
    if (mp < M) {
        int s = nc * M + mp;
        v1 = d1[s];
        v2 = d2[s];
    }
    d_D1p[idx] = v1;
    d_D2p[idx] = v2;
}

// ---------------------------------------------------------------------------
// vm[n, i, j] = product of the 8x8 block of vis_mask1 (space_to_depth prod).
// Padded entries (mp >= 3600) are 0, which also kills padded GEMM columns.
// ---------------------------------------------------------------------------
__global__ void vm_kernel(const float* __restrict__ vis) {
    int idx = blockIdx.x * blockDim.x + threadIdx.x;
    if (idx >= NB * MP) return;
    int mp = idx % MP;
    int n  = idx / MP;
    float p = 0.f;
    if (mp < M) {
        int i = mp / WR, j = mp % WR;
        p = 1.f;
        const float* base = vis + n * HH * WW + (i * GS) * WW + j * GS;
        #pragma unroll
        for (int a = 0; a < GS; a++)
            #pragma unroll
            for (int b = 0; b < GS; b++)
                p *= base[a * WW + b];
    }
    d_vm[idx] = p;
}

// ---------------------------------------------------------------------------
// Fused GEMM + negative-hinge + reduce.
// S = D1^T * D2 per image (3712x3712, K=256), tile 128x128,
// epilogue: partial += vm[col] * max(S - 0.2, 0), one float per block.
// ---------------------------------------------------------------------------
__global__ __launch_bounds__(256, 2) void gemm_loss_kernel() {
    int n = blockIdx.z;
    const float* Ab = d_D1p + n * C * MP + blockIdx.y * BM;
    const float* Bb = d_D2p + n * C * MP + blockIdx.x * BN;

    __shared__ float As[2][BK][BM];
    __shared__ float Bs[2][BK][BN];

    int tid  = threadIdx.x;
    int tx   = tid & 15;        // 16 cols of threads
    int ty   = tid >> 4;        // 16 rows of threads
    int lrow = tid >> 5;        // loader: k-row 0..7
    int lcol = (tid & 31) << 2; // loader: col 0..124 (float4)

    float acc[8][8];
    #pragma unroll
    for (int i = 0; i < 8; i++)
        #pragma unroll
        for (int j = 0; j < 8; j++) acc[i][j] = 0.f;

    // prologue: fill buffer 0
    *(float4*)&As[0][lrow][lcol] = *(const float4*)&Ab[lrow * MP + lcol];
    *(float4*)&Bs[0][lrow][lcol] = *(const float4*)&Bb[lrow * MP + lcol];
    __syncthreads();

    #pragma unroll 1
    for (int k0 = 0; k0 < C; k0 += BK) {
        int buf = (k0 >> 3) & 1;
        if (k0 + BK < C) {
            *(float4*)&As[buf ^ 1][lrow][lcol] =
                *(const float4*)&Ab[(k0 + BK + lrow) * MP + lcol];
            *(float4*)&Bs[buf ^ 1][lrow][lcol] =
                *(const float4*)&Bb[(k0 + BK + lrow) * MP + lcol];
        }
        #pragma unroll
        for (int kk = 0; kk < BK; kk++) {
            float a[8], b[8];
            *(float4*)&a[0] = *(const float4*)&As[buf][kk][ty * 8];
            *(float4*)&a[4] = *(const float4*)&As[buf][kk][ty * 8 + 4];
            *(float4*)&b[0] = *(const float4*)&Bs[buf][kk][tx * 8];
            *(float4*)&b[4] = *(const float4*)&Bs[buf][kk][tx * 8 + 4];
            #pragma unroll
            for (int i = 0; i < 8; i++)
                #pragma unroll
                for (int j = 0; j < 8; j++)
                    acc[i][j] = fmaf(a[i], b[j], acc[i][j]);
        }
        __syncthreads();
    }

    // epilogue: hinge + vm weight + reduce to one partial per block
    float vmv[8];
    #pragma unroll
    for (int j = 0; j < 8; j++)
        vmv[j] = d_vm[n * MP + blockIdx.x * BN + tx * 8 + j];

    float local = 0.f;
    #pragma unroll
    for (int i = 0; i < 8; i++)
        #pragma unroll
        for (int j = 0; j < 8; j++)
            local += vmv[j] * fmaxf(acc[i][j] - 0.2f, 0.f);

    #pragma unroll
    for (int o = 16; o > 0; o >>= 1)
        local += __shfl_down_sync(0xffffffffu, local, o);

    __shared__ float wsum[8];
    if ((tid & 31) == 0) wsum[tid >> 5] = local;
    __syncthreads();
    if (tid == 0) {
        float t = 0.f;
        #pragma unroll
        for (int w = 0; w < 8; w++) t += wsum[w];
        d_partA[(blockIdx.z * GB + blockIdx.y) * GB + blockIdx.x] = t;
    }
}

// ---------------------------------------------------------------------------
// Positive-pair correction: for each (n,i,j), warp the cell center by the
// homography, find the (at most ~4) cells whose center is within 7.5 px,
// compute those dot products directly, add vm*(max(1-d,0) - max(d-0.2,0)).
// One warp per (n,i,j); 8 warps per block.
// ---------------------------------------------------------------------------
__global__ void pos_kernel(const float* __restrict__ d1,
                           const float* __restrict__ d2,
                           const float* __restrict__ homo) {
    int warp = threadIdx.x >> 5;
    int lane = threadIdx.x & 31;
    int item = blockIdx.x * 8 + warp;   // 0 .. 14399
    float contrib = 0.f;

    if (item < NB * M) {
        int n  = item / M;
        int ij = item % M;
        int i  = ij / WR, j = ij % WR;
        float x = j * 8 + 4.f, y = i * 8 + 4.f;
        const float* Hm = homo + n * 9;
        float wxh = Hm[0] * x + Hm[1] * y + Hm[2];
        float wyh = Hm[3] * x + Hm[4] * y + Hm[5];
        float wzh = Hm[6] * x + Hm[7] * y + Hm[8];
        float wx = wxh / wzh, wy = wyh / wzh;
        float vmv = d_vm[n * MP + ij];

        int hs = (int)floorf((wy - 11.5f) * 0.125f);
        int ws = (int)floorf((wx - 11.5f) * 0.125f);
        for (int hh = hs; hh < hs + 4; hh++) {
            if (hh < 0 || hh >= HR) continue;
            float dy = hh * 8 + 4.f - wy;
            for (int wc = ws; wc < ws + 4; wc++) {
                if (wc < 0 || wc >= WR) continue;
                float dx = wc * 8 + 4.f - wx;
                if (dx * dx + dy * dy <= 56.25f) {   // dist <= 7.5
                    const float* p1 = d1 + n * C * M + hh * WR + wc;
                    const float* p2 = d2 + n * C * M + ij;
                    float dt = 0.f;
                    for (int c = lane; c < C; c += 32)
                        dt += p1[c * M] * p2[c * M];
                    #pragma unroll
                    for (int o = 16; o > 0; o >>= 1)
                        dt += __shfl_down_sync(0xffffffffu, dt, o);
                    dt = __shfl_sync(0xffffffffu, dt, 0);
                    if (lane == 0)
                        contrib += vmv * (fmaxf(1.f - dt, 0.f) - fmaxf(dt - 0.2f, 0.f));
                }
            }
        }
    }

    __shared__ float wsh[8];
    if (lane == 0) wsh[warp] = contrib;
    __syncthreads();
    if (threadIdx.x == 0) {
        float t = 0.f;
        #pragma unroll
        for (int w = 0; w < 8; w++) t += wsh[w];
        d_partB[blockIdx.x] = t;
    }
}

// ---------------------------------------------------------------------------
// Final deterministic reduction: sum all partials + vm.sum(), normalize.
// ---------------------------------------------------------------------------
__global__ void final_kernel(float* __restrict__ out) {
    __shared__ float sh[256];
    int tid = threadIdx.x;

    float s = 0.f;
    for (int k = tid; k < GB * GB * NB; k += 256) s += d_partA[k];
    for (int k = tid; k < NPOSB; k += 256) s += d_partB[k];
    float v = 0.f;
    for (int k = tid; k < NB * MP; k += 256) v += d_vm[k];  // pads are 0

    sh[tid] = s;
    __syncthreads();
    for (int o = 128; o > 0; o >>= 1) {
        if (tid < o) sh[tid] += sh[tid + o];
        __syncthreads();
    }
    float total = sh[0];
    __syncthreads();

    sh[tid] = v;
    __syncthreads();
    for (int o = 128; o > 0; o >>= 1) {
        if (tid < o) sh[tid] += sh[tid + o];
        __syncthreads();
    }
    if (tid == 0)
        out[0] = total / (3600.f * sh[0]);   // LOSS_LAMBDA = 1
}

// ---------------------------------------------------------------------------
extern "C" void kernel_launch(void* const* d_in, const int* in_sizes, int n_in,
                              void* d_out, int out_size) {
    // Robust input mapping by element count:
    //   desc1/desc2: 4*256*60*60 = 3686400 (order preserved among equals)
    //   homo21:      4*3*3      = 36
    //   vis_mask1:   4*1*480*480 = 921600
    const float* desc1 = nullptr;
    const float* desc2 = nullptr;
    const float* homo  = nullptr;
    const float* vis   = nullptr;
    for (int k = 0; k < n_in; k++) {
        if (in_sizes[k] == NB * C * M) {
            if (!desc1) desc1 = (const float*)d_in[k];
            else if (!desc2) desc2 = (const float*)d_in[k];
        } else if (in_sizes[k] == NB * 9) {
            homo = (const float*)d_in[k];
        } else if (in_sizes[k] == NB * HH * WW) {
            vis = (const float*)d_in[k];
        }
    }

    pad_kernel<<<(NB * C * MP + 255) / 256, 256>>>(desc1, desc2);
    vm_kernel<<<(NB * MP + 255) / 256, 256>>>(vis);
    gemm_loss_kernel<<<dim3(GB, GB, NB), 256>>>();
    pos_kernel<<<NPOSB, 256>>>(desc1, desc2, homo);
    final_kernel<<<1, 256>>>((float*)d_out);
}

// round 4
// speedup vs baseline: 4.7149x; 4.7149x over previous
#include <cuda_runtime.h>
#include <cuda_bf16.h>
#include <cstdint>

// ---------------------------------------------------------------------------
// Arch feature gate: tcgen05 / TMEM are "a"-target-only features. The harness
// may compile a plain compute_103 pass that rejects them, so every tcgen05
// instruction is guarded. Exactly one of the two GEMM kernels is active in
// any given compiled pass; the other compiles to a no-op.
// ---------------------------------------------------------------------------
#if defined(__CUDA_ARCH__) && (defined(__CUDA_ARCH_FEAT_SM103_ALL) || defined(__CUDA_ARCH_FEAT_SM100_ALL))
#define HAS_TC 1
#else
#define HAS_TC 0
#endif

// Problem constants
#define NB 4
#define C  256
#define HR 60
#define WR 60
#define M  3600          // HR*WR
#define MP 3712          // padded to 29*128
#define GS 8
#define HH 480
#define WW 480

#define BM 128
#define BN 128
#define BK 8
#define GB 29
#define NPOSB 1800

// idesc kind::f16: dtype=F32(1<<4), atype=BF16(1<<7), btype=BF16(1<<10),
// N/8 << 17, M/16 << 24  ->  M=128, N=128
#define MMA_IDESC 0x8200490u

// __device__ scratch (no allocation allowed)
__device__ __nv_bfloat16 d_D1t[(size_t)NB * MP * C];   // [n][m][c] bf16, zero-padded rows
__device__ __nv_bfloat16 d_D2t[(size_t)NB * MP * C];
__device__ float d_D1p[NB * C * MP];                   // fp32 [n][c][m] padded (fallback)
__device__ float d_D2p[NB * C * MP];
__device__ float d_vm[NB * MP];
__device__ float d_partA[GB * GB * NB];
__device__ float d_partB[NPOSB];

// ---------------------------------------------------------------------------
// Helpers
// ---------------------------------------------------------------------------
__device__ __forceinline__ uint32_t smem_u32(const void* p) {
    uint32_t a;
    asm("{ .reg .u64 t; cvta.to.shared.u64 t, %1; cvt.u32.u64 %0, t; }" : "=r"(a) : "l"(p));
    return a;
}
#define SWZ128(off) ((off) ^ (((off) >> 3) & 0x70))

#if HAS_TC
__device__ __forceinline__ uint32_t elect_one() {
    uint32_t p;
    asm volatile("{ .reg .pred p; elect.sync _|p, 0xFFFFFFFF; selp.b32 %0, 1, 0, p; }" : "=r"(p));
    return p;
}
static __device__ __forceinline__ uint64_t make_desc(uint32_t addr) {
    // SW128, version=1(Blackwell), SBO=64, LBO=1
    const uint64_t base = (uint64_t(2) << 61) | (uint64_t(1) << 46)
                        | (uint64_t(64) << 32) | (uint64_t(1) << 16);
    return base | ((uint64_t)(addr >> 4) & 0x3FFF);
}
__device__ __forceinline__ void mma_f16_ss_cg1(uint32_t d_tmem, uint64_t a_desc,
                                               uint64_t b_desc, uint32_t idesc,
                                               uint32_t enable) {
    asm volatile(
        "{\n\t.reg .pred p;\n\t"
        "setp.ne.u32 p, %4, 0;\n\t"
        "tcgen05.mma.cta_group::1.kind::f16 [%0], %1, %2, %3, {%5, %5, %5, %5}, p;\n\t}"
        :: "r"(d_tmem), "l"(a_desc), "l"(b_desc), "r"(idesc), "r"(enable), "r"(0u)
        : "memory");
}
#endif

// ---------------------------------------------------------------------------
// Transpose + pad + bf16 convert: [n][c][m] f32 -> [n][m][c] bf16 (rows m>=M zero)
// Runs on every arch (feeds pos_kernel always, gemm_tc on "a" targets).
// ---------------------------------------------------------------------------
__global__ void transpose_kernel(const float* __restrict__ d1,
                                 const float* __restrict__ d2) {
    __shared__ float t1[32][33];
    __shared__ float t2[32][33];
    int m0 = blockIdx.x * 32, c0 = blockIdx.y * 32, n = blockIdx.z;
    int tx = threadIdx.x, ty = threadIdx.y;   // 32 x 8

    #pragma unroll
    for (int i = 0; i < 4; i++) {
        int c = c0 + ty + i * 8, m = m0 + tx;
        float v1 = 0.f, v2 = 0.f;
        if (m < M) {
            size_t idx = ((size_t)n * C + c) * M + m;
            v1 = d1[idx]; v2 = d2[idx];
        }
        t1[ty + i * 8][tx] = v1;
        t2[ty + i * 8][tx] = v2;
    }
    __syncthreads();
    #pragma unroll
    for (int i = 0; i < 4; i++) {
        int m = m0 + ty + i * 8, c = c0 + tx;
        if (m < MP) {
            size_t o = ((size_t)n * MP + m) * C + c;
            d_D1t[o] = __float2bfloat16(t1[tx][ty + i * 8]);
            d_D2t[o] = __float2bfloat16(t2[tx][ty + i * 8]);
        }
    }
}

// ---------------------------------------------------------------------------
// Fallback prep: zero-padded fp32 copies [n][c][m]. No-op on "a" targets.
// ---------------------------------------------------------------------------
__global__ void pad_kernel(const float* __restrict__ d1, const float* __restrict__ d2) {
#if !HAS_TC
    int idx = blockIdx.x * blockDim.x + threadIdx.x;
    if (idx >= NB * C * MP) return;
    int mp = idx % MP;
    int nc = idx / MP;
    float v1 = 0.f, v2 = 0.f;
    if (mp < M) {
        int s = nc * M + mp;
        v1 = d1[s];
        v2 = d2[s];
    }
    d_D1p[idx] = v1;
    d_D2p[idx] = v2;
#endif
}

// ---------------------------------------------------------------------------
// vm[n, i, j] = prod of 8x8 block of vis_mask1; padded entries are 0.
// ---------------------------------------------------------------------------
__global__ void vm_kernel(const float* __restrict__ vis) {
    int idx = blockIdx.x * blockDim.x + threadIdx.x;
    if (idx >= NB * MP) return;
    int mp = idx % MP;
    int n  = idx / MP;
    float p = 0.f;
    if (mp < M) {
        int i = mp / WR, j = mp % WR;
        p = 1.f;
        const float* base = vis + n * HH * WW + (i * GS) * WW + j * GS;
        #pragma unroll
        for (int a = 0; a < GS; a++)
            #pragma unroll
            for (int b = 0; b < GS; b++)
                p *= base[a * WW + b];
    }
    d_vm[idx] = p;
}

// ---------------------------------------------------------------------------
// tcgen05 GEMM + neg-hinge + reduce (active only on sm_103a/sm_100a cubins).
// Tile 128x128, K=256 in 4 chunks of 64. A/B K-major bf16, SW128.
// ---------------------------------------------------------------------------
__global__ __launch_bounds__(128, 1) void gemm_tc_kernel() {
#if HAS_TC
    extern __shared__ char dyn_sm[];
    __shared__ uint32_t s_tmem[1];
    __shared__ __align__(8) unsigned long long s_mbar;
    __shared__ float s_vm[BN];
    __shared__ float s_red[4];

    const int n   = blockIdx.z;
    const int tid = threadIdx.x;
    const int wid = tid >> 5, lid = tid & 31;

    // 1024-aligned dynamic smem base: A chunks at +0 (64KB), B at +65536 (64KB)
    uint32_t raw  = smem_u32(dyn_sm);
    uint32_t base = (raw + 1023u) & ~1023u;
    char* smp = dyn_sm + (base - raw);

    bool leader = false;
    if (wid == 0) {
        asm volatile("tcgen05.alloc.cta_group::1.sync.aligned.shared::cta.b32 [%0], %1;"
                     :: "r"(smem_u32(s_tmem)), "r"(128u) : "memory");
        asm volatile("tcgen05.relinquish_alloc_permit.cta_group::1.sync.aligned;");
        leader = elect_one() != 0;
    }
    if (tid == 0) {
        asm volatile("mbarrier.init.shared.b64 [%0], %1;"
                     :: "r"(smem_u32(&s_mbar)), "r"(1u) : "memory");
    }
    s_vm[tid] = d_vm[n * MP + blockIdx.x * BN + tid];
    __syncthreads();
    uint32_t tmem = s_tmem[0];
    uint32_t mbar = smem_u32(&s_mbar);

    const __nv_bfloat16* Ag = d_D1t + ((size_t)n * MP + blockIdx.y * BM) * C;
    const __nv_bfloat16* Bg = d_D2t + ((size_t)n * MP + blockIdx.x * BN) * C;

    const int r0 = tid >> 3;        // 0..15
    const int v  = tid & 7;         // 16B vector within 128B chunk-row

    #pragma unroll 1
    for (int c = 0; c < 4; c++) {
        // load chunk c: 128 rows x 64 bf16 (128B/row) per operand
        #pragma unroll
        for (int i = 0; i < 8; i++) {
            int r = r0 + i * 16;
            const uint4 av = *(const uint4*)(Ag + (size_t)r * C + c * 64 + v * 8);
            const uint4 bv = *(const uint4*)(Bg + (size_t)r * C + c * 64 + v * 8);
            uint32_t off = SWZ128((uint32_t)(r * 128 + v * 16));
            *(uint4*)(smp + c * 16384 + off)         = av;
            *(uint4*)(smp + 65536 + c * 16384 + off) = bv;
        }
        asm volatile("fence.proxy.async.shared::cta;" ::: "memory");
        __syncthreads();
        if (leader) {
            uint64_t ad = make_desc(base + c * 16384);
            uint64_t bd = make_desc(base + 65536 + c * 16384);
            #pragma unroll
            for (int ks = 0; ks < 4; ks++)
                mma_f16_ss_cg1(tmem, ad + ks * 2, bd + ks * 2, MMA_IDESC,
                               (uint32_t)(c * 4 + ks));   // first MMA overwrites
        }
    }
    if (leader) {
        asm volatile(
            "tcgen05.commit.cta_group::1.mbarrier::arrive::one.shared::cluster.b64 [%0];"
            :: "r"(mbar) : "memory");
    }

    // wait for MMA completion
    {
        uint32_t done;
        asm volatile(
            "{\n\t.reg .pred p;\n\t"
            "mbarrier.try_wait.parity.acquire.cta.shared::cta.b64 p, [%1], %2;\n\t"
            "selp.b32 %0, 1, 0, p;\n\t}"
            : "=r"(done) : "r"(mbar), "r"(0u) : "memory");
        if (!done) {
            asm volatile(
                "{\n\t.reg .pred P1;\n\t"
                "WL_%=:\n\t"
                "mbarrier.try_wait.parity.acquire.cta.shared::cta.b64 P1, [%0], %1, 0x989680;\n\t"
                "@P1 bra.uni WD_%=;\n\t"
                "bra.uni WL_%=;\n\t"
                "WD_%=:\n\t}"
                :: "r"(mbar), "r"(0u) : "memory");
        }
    }
    asm volatile("tcgen05.fence::after_thread_sync;" ::: "memory");

    // epilogue: hinge + vm weight + reduce (each warp reads its 32-row subpartition)
    float local = 0.f;
    #pragma unroll 1
    for (int cb = 0; cb < 4; cb++) {
        uint32_t dr[32];
        asm volatile(
            "tcgen05.ld.sync.aligned.32x32b.x32.b32 "
            "{%0, %1, %2, %3, %4, %5, %6, %7, "
            " %8, %9, %10, %11, %12, %13, %14, %15, "
            " %16, %17, %18, %19, %20, %21, %22, %23, "
            " %24, %25, %26, %27, %28, %29, %30, %31}, [%32];"
            : "=r"(dr[0]),  "=r"(dr[1]),  "=r"(dr[2]),  "=r"(dr[3]),
              "=r"(dr[4]),  "=r"(dr[5]),  "=r"(dr[6]),  "=r"(dr[7]),
              "=r"(dr[8]),  "=r"(dr[9]),  "=r"(dr[10]), "=r"(dr[11]),
              "=r"(dr[12]), "=r"(dr[13]), "=r"(dr[14]), "=r"(dr[15]),
              "=r"(dr[16]), "=r"(dr[17]), "=r"(dr[18]), "=r"(dr[19]),
              "=r"(dr[20]), "=r"(dr[21]), "=r"(dr[22]), "=r"(dr[23]),
              "=r"(dr[24]), "=r"(dr[25]), "=r"(dr[26]), "=r"(dr[27]),
              "=r"(dr[28]), "=r"(dr[29]), "=r"(dr[30]), "=r"(dr[31])
            : "r"(tmem + cb * 32));
        asm volatile("tcgen05.wait::ld.sync.aligned;" ::: "memory");
        #pragma unroll
        for (int j = 0; j < 32; j++)
            local += s_vm[cb * 32 + j] * fmaxf(__uint_as_float(dr[j]) - 0.2f, 0.f);
    }

    #pragma unroll
    for (int o = 16; o > 0; o >>= 1)
        local += __shfl_down_sync(0xffffffffu, local, o);
    if (lid == 0) s_red[wid] = local;
    __syncthreads();
    if (tid == 0)
        d_partA[(blockIdx.z * GB + blockIdx.y) * GB + blockIdx.x]
            = s_red[0] + s_red[1] + s_red[2] + s_red[3];

    if (wid == 0) {
        asm volatile("tcgen05.dealloc.cta_group::1.sync.aligned.b32 %0, %1;"
                     :: "r"(tmem), "r"(128u));
    }
#endif
}

// ---------------------------------------------------------------------------
// Fallback SIMT fp32 GEMM + neg-hinge + reduce (active only WITHOUT tcgen05).
// Same tiling as the round-1 661us kernel.
// ---------------------------------------------------------------------------
__global__ __launch_bounds__(256, 2) void gemm_simt_kernel() {
#if !HAS_TC
    int n = blockIdx.z;
    const float* Ab = d_D1p + n * C * MP + blockIdx.y * BM;
    const float* Bb = d_D2p + n * C * MP + blockIdx.x * BN;

    __shared__ float As[2][BK][BM];
    __shared__ float Bs[2][BK][BN];

    int tid  = threadIdx.x;
    int tx   = tid & 15;
    int ty   = tid >> 4;
    int lrow = tid >> 5;
    int lcol = (tid & 31) << 2;

    float acc[8][8];
    #pragma unroll
    for (int i = 0; i < 8; i++)
        #pragma unroll
        for (int j = 0; j < 8; j++) acc[i][j] = 0.f;

    *(float4*)&As[0][lrow][lcol] = *(const float4*)&Ab[lrow * MP + lcol];
    *(float4*)&Bs[0][lrow][lcol] = *(const float4*)&Bb[lrow * MP + lcol];
    __syncthreads();

    #pragma unroll 1
    for (int k0 = 0; k0 < C; k0 += BK) {
        int buf = (k0 >> 3) & 1;
        if (k0 + BK < C) {
            *(float4*)&As[buf ^ 1][lrow][lcol] =
                *(const float4*)&Ab[(k0 + BK + lrow) * MP + lcol];
            *(float4*)&Bs[buf ^ 1][lrow][lcol] =
                *(const float4*)&Bb[(k0 + BK + lrow) * MP + lcol];
        }
        #pragma unroll
        for (int kk = 0; kk < BK; kk++) {
            float a[8], b[8];
            *(float4*)&a[0] = *(const float4*)&As[buf][kk][ty * 8];
            *(float4*)&a[4] = *(const float4*)&As[buf][kk][ty * 8 + 4];
            *(float4*)&b[0] = *(const float4*)&Bs[buf][kk][tx * 8];
            *(float4*)&b[4] = *(const float4*)&Bs[buf][kk][tx * 8 + 4];
            #pragma unroll
            for (int i = 0; i < 8; i++)
                #pragma unroll
                for (int j = 0; j < 8; j++)
                    acc[i][j] = fmaf(a[i], b[j], acc[i][j]);
        }
        __syncthreads();
    }

    float vmv[8];
    #pragma unroll
    for (int j = 0; j < 8; j++)
        vmv[j] = d_vm[n * MP + blockIdx.x * BN + tx * 8 + j];

    float local = 0.f;
    #pragma unroll
    for (int i = 0; i < 8; i++)
        #pragma unroll
        for (int j = 0; j < 8; j++)
            local += vmv[j] * fmaxf(acc[i][j] - 0.2f, 0.f);

    #pragma unroll
    for (int o = 16; o > 0; o >>= 1)
        local += __shfl_down_sync(0xffffffffu, local, o);

    __shared__ float wsum[8];
    if ((tid & 31) == 0) wsum[tid >> 5] = local;
    __syncthreads();
    if (tid == 0) {
        float t = 0.f;
        #pragma unroll
        for (int w = 0; w < 8; w++) t += wsum[w];
        d_partA[(blockIdx.z * GB + blockIdx.y) * GB + blockIdx.x] = t;
    }
#endif
}

// ---------------------------------------------------------------------------
// Positive-pair correction on transposed bf16 arrays (coalesced dots).
// ---------------------------------------------------------------------------
__device__ __forceinline__ float dot8(uint4 a, uint4 b) {
    const __nv_bfloat162* pa = (const __nv_bfloat162*)&a;
    const __nv_bfloat162* pb = (const __nv_bfloat162*)&b;
    float s = 0.f;
    #pragma unroll
    for (int k = 0; k < 4; k++) {
        float2 fa = __bfloat1622float2(pa[k]);
        float2 fb = __bfloat1622float2(pb[k]);
        s += fa.x * fb.x + fa.y * fb.y;
    }
    return s;
}

__global__ void pos_kernel(const float* __restrict__ homo) {
    int warp = threadIdx.x >> 5;
    int lane = threadIdx.x & 31;
    int item = blockIdx.x * 8 + warp;   // 0 .. 14399
    float contrib = 0.f;

    if (item < NB * M) {
        int n  = item / M;
        int ij = item % M;
        int i  = ij / WR, j = ij % WR;
        float x = j * 8 + 4.f, y = i * 8 + 4.f;
        const float* Hm = homo + n * 9;
        float wxh = Hm[0] * x + Hm[1] * y + Hm[2];
        float wyh = Hm[3] * x + Hm[4] * y + Hm[5];
        float wzh = Hm[6] * x + Hm[7] * y + Hm[8];
        float wx = wxh / wzh, wy = wyh / wzh;
        float vmv = d_vm[n * MP + ij];

        const uint4 bvec = ((const uint4*)(d_D2t + ((size_t)n * MP + ij) * C))[lane];

        int hs = (int)floorf((wy - 11.5f) * 0.125f);
        int ws = (int)floorf((wx - 11.5f) * 0.125f);
        for (int hh = hs; hh < hs + 4; hh++) {
            if (hh < 0 || hh >= HR) continue;
            float dy = hh * 8 + 4.f - wy;
            for (int wc = ws; wc < ws + 4; wc++) {
                if (wc < 0 || wc >= WR) continue;
                float dx = wc * 8 + 4.f - wx;
                if (dx * dx + dy * dy <= 56.25f) {   // dist <= 7.5
                    const uint4 avec =
                        ((const uint4*)(d_D1t + ((size_t)n * MP + hh * WR + wc) * C))[lane];
                    float dt = dot8(avec, bvec);
                    #pragma unroll
                    for (int o = 16; o > 0; o >>= 1)
                        dt += __shfl_down_sync(0xffffffffu, dt, o);
                    dt = __shfl_sync(0xffffffffu, dt, 0);
                    if (lane == 0)
                        contrib += vmv * (fmaxf(1.f - dt, 0.f) - fmaxf(dt - 0.2f, 0.f));
                }
            }
        }
    }

    __shared__ float wsh[8];
    if (lane == 0) wsh[warp] = contrib;
    __syncthreads();
    if (threadIdx.x == 0) {
        float t = 0.f;
        #pragma unroll
        for (int w = 0; w < 8; w++) t += wsh[w];
        d_partB[blockIdx.x] = t;
    }
}

// ---------------------------------------------------------------------------
// Final deterministic reduction.
// ---------------------------------------------------------------------------
__global__ void final_kernel(float* __restrict__ out) {
    __shared__ float sh[256];
    int tid = threadIdx.x;

    float s = 0.f;
    for (int k = tid; k < GB * GB * NB; k += 256) s += d_partA[k];
    for (int k = tid; k < NPOSB; k += 256) s += d_partB[k];
    float v = 0.f;
    for (int k = tid; k < NB * MP; k += 256) v += d_vm[k];  // pads are 0

    sh[tid] = s;
    __syncthreads();
    for (int o = 128; o > 0; o >>= 1) {
        if (tid < o) sh[tid] += sh[tid + o];
        __syncthreads();
    }
    float total = sh[0];
    __syncthreads();

    sh[tid] = v;
    __syncthreads();
    for (int o = 128; o > 0; o >>= 1) {
        if (tid < o) sh[tid] += sh[tid + o];
        __syncthreads();
    }
    if (tid == 0)
        out[0] = total / (3600.f * sh[0]);   // LOSS_LAMBDA = 1
}

// ---------------------------------------------------------------------------
extern "C" void kernel_launch(void* const* d_in, const int* in_sizes, int n_in,
                              void* d_out, int out_size) {
    const float* desc1 = nullptr;
    const float* desc2 = nullptr;
    const float* homo  = nullptr;
    const float* vis   = nullptr;
    for (int k = 0; k < n_in; k++) {
        if (in_sizes[k] == NB * C * M) {
            if (!desc1) desc1 = (const float*)d_in[k];
            else if (!desc2) desc2 = (const float*)d_in[k];
        } else if (in_sizes[k] == NB * 9) {
            homo = (const float*)d_in[k];
        } else if (in_sizes[k] == NB * HH * WW) {
            vis = (const float*)d_in[k];
        }
    }

    // Idempotent, capture-safe (not a stream op); no static state allowed.
    cudaFuncSetAttribute(gemm_tc_kernel,
                         cudaFuncAttributeMaxDynamicSharedMemorySize, 132096);

    transpose_kernel<<<dim3(116, 8, NB), dim3(32, 8)>>>(desc1, desc2);
    vm_kernel<<<(NB * MP + 255) / 256, 256>>>(vis);
    pad_kernel<<<(NB * C * MP + 255) / 256, 256>>>(desc1, desc2);   // no-op on "a" targets
    gemm_tc_kernel<<<dim3(GB, GB, NB), 128, 132096>>>();            // active on "a" targets
    gemm_simt_kernel<<<dim3(GB, GB, NB), 256>>>();                  // active otherwise
    pos_kernel<<<NPOSB, 256>>>(homo);
    final_kernel<<<1, 256>>>((float*)d_out);
}

// round 5
// speedup vs baseline: 8.0530x; 1.7080x over previous
#include <cuda_runtime.h>
#include <cuda_bf16.h>
#include <cstdint>

// ---------------------------------------------------------------------------
// Arch feature gate: tcgen05/TMEM are "a"-target-only. Non-"a" passes compile
// the SIMT fallback instead; exactly one GEMM kernel is active per pass.
// ---------------------------------------------------------------------------
#if defined(__CUDA_ARCH__) && (defined(__CUDA_ARCH_FEAT_SM103_ALL) || defined(__CUDA_ARCH_FEAT_SM100_ALL))
#define HAS_TC 1
#else
#define HAS_TC 0
#endif

// Problem constants
#define NB 4
#define C  256
#define HR 60
#define WR 60
#define M  3600          // HR*WR
#define MP 3712          // padded to 29*128
#define GS 8
#define HH 480
#define WW 480

#define BM 128
#define BN 128
#define BK 8
#define GB 29            // tiles per GEMM dim
#define NT 29            // A tiles per strip (persistent loop)
#define NPOSB 1800

// idesc kind::f16: dtype=F32(1<<4), atype=BF16(1<<7), btype=BF16(1<<10),
// N/8 << 17, M/16 << 24  ->  M=128, N=128
#define MMA_IDESC 0x8200490u

// __device__ scratch (no allocation allowed)
__device__ __align__(16) __nv_bfloat16 d_D1t[(size_t)NB * MP * C];  // [n][m][c] bf16
__device__ __align__(16) __nv_bfloat16 d_D2t[(size_t)NB * MP * C];
__device__ float d_D1p[NB * C * MP];                                // fp32 fallback
__device__ float d_D2p[NB * C * MP];
__device__ float d_vm[NB * MP];
__device__ float d_partA[GB * GB * NB];
__device__ float d_partB[NPOSB];

// ---------------------------------------------------------------------------
// Helpers
// ---------------------------------------------------------------------------
__device__ __forceinline__ uint32_t smem_u32(const void* p) {
    uint32_t a;
    asm("{ .reg .u64 t; cvta.to.shared.u64 t, %1; cvt.u32.u64 %0, t; }" : "=r"(a) : "l"(p));
    return a;
}
#define SWZ128(off) ((off) ^ (((off) >> 3) & 0x70))

__device__ __forceinline__ void cp_async16(uint32_t dst, const void* src) {
    asm volatile("cp.async.cg.shared.global [%0], [%1], 16;"
                 :: "r"(dst), "l"(src) : "memory");
}
__device__ __forceinline__ void cp_async_wait_all() {
    asm volatile("cp.async.wait_all;" ::: "memory");
}

#if HAS_TC
__device__ __forceinline__ uint32_t elect_one() {
    uint32_t p;
    asm volatile("{ .reg .pred p; elect.sync _|p, 0xFFFFFFFF; selp.b32 %0, 1, 0, p; }" : "=r"(p));
    return p;
}
static __device__ __forceinline__ uint64_t make_desc(uint32_t addr) {
    // SW128, version=1(Blackwell), SBO=64, LBO=1
    const uint64_t base = (uint64_t(2) << 61) | (uint64_t(1) << 46)
                        | (uint64_t(64) << 32) | (uint64_t(1) << 16);
    return base | ((uint64_t)(addr >> 4) & 0x3FFF);
}
__device__ __forceinline__ void mma_f16_ss_cg1(uint32_t d_tmem, uint64_t a_desc,
                                               uint64_t b_desc, uint32_t idesc,
                                               uint32_t enable) {
    asm volatile(
        "{\n\t.reg .pred p;\n\t"
        "setp.ne.u32 p, %4, 0;\n\t"
        "tcgen05.mma.cta_group::1.kind::f16 [%0], %1, %2, %3, {%5, %5, %5, %5}, p;\n\t}"
        :: "r"(d_tmem), "l"(a_desc), "l"(b_desc), "r"(idesc), "r"(enable), "r"(0u)
        : "memory");
}
__device__ __forceinline__ void mbar_wait(uint32_t mbar, uint32_t parity) {
    uint32_t done;
    asm volatile(
        "{\n\t.reg .pred p;\n\t"
        "mbarrier.try_wait.parity.acquire.cta.shared::cta.b64 p, [%1], %2;\n\t"
        "selp.b32 %0, 1, 0, p;\n\t}"
        : "=r"(done) : "r"(mbar), "r"(parity) : "memory");
    if (!done) {
        asm volatile(
            "{\n\t.reg .pred P1;\n\t"
            "WL_%=:\n\t"
            "mbarrier.try_wait.parity.acquire.cta.shared::cta.b64 P1, [%0], %1, 0x989680;\n\t"
            "@P1 bra.uni WD_%=;\n\t"
            "bra.uni WL_%=;\n\t"
            "WD_%=:\n\t}"
            :: "r"(mbar), "r"(parity) : "memory");
    }
}
#endif

// ---------------------------------------------------------------------------
// Transpose + pad + bf16 convert: [n][c][m] f32 -> [n][m][c] bf16
// ---------------------------------------------------------------------------
__global__ void transpose_kernel(const float* __restrict__ d1,
                                 const float* __restrict__ d2) {
    __shared__ float t1[32][33];
    __shared__ float t2[32][33];
    int m0 = blockIdx.x * 32, c0 = blockIdx.y * 32, n = blockIdx.z;
    int tx = threadIdx.x, ty = threadIdx.y;   // 32 x 8

    #pragma unroll
    for (int i = 0; i < 4; i++) {
        int c = c0 + ty + i * 8, m = m0 + tx;
        float v1 = 0.f, v2 = 0.f;
        if (m < M) {
            size_t idx = ((size_t)n * C + c) * M + m;
            v1 = d1[idx]; v2 = d2[idx];
        }
        t1[ty + i * 8][tx] = v1;
        t2[ty + i * 8][tx] = v2;
    }
    __syncthreads();
    #pragma unroll
    for (int i = 0; i < 4; i++) {
        int m = m0 + ty + i * 8, c = c0 + tx;
        if (m < MP) {
            size_t o = ((size_t)n * MP + m) * C + c;
            d_D1t[o] = __float2bfloat16(t1[tx][ty + i * 8]);
            d_D2t[o] = __float2bfloat16(t2[tx][ty + i * 8]);
        }
    }
}

// ---------------------------------------------------------------------------
// Fallback prep (no-op on "a" targets)
// ---------------------------------------------------------------------------
__global__ void pad_kernel(const float* __restrict__ d1, const float* __restrict__ d2) {
#if !HAS_TC
    int idx = blockIdx.x * blockDim.x + threadIdx.x;
    if (idx >= NB * C * MP) return;
    int mp = idx % MP;
    int nc = idx / MP;
    float v1 = 0.f, v2 = 0.f;
    if (mp < M) {
        int s = nc * M + mp;
        v1 = d1[s];
        v2 = d2[s];
    }
    d_D1p[idx] = v1;
    d_D2p[idx] = v2;
#endif
}

// ---------------------------------------------------------------------------
// vm[n, i, j] = prod of 8x8 block of vis_mask1; padded entries are 0.
// ---------------------------------------------------------------------------
__global__ void vm_kernel(const float* __restrict__ vis) {
    int idx = blockIdx.x * blockDim.x + threadIdx.x;
    if (idx >= NB * MP) return;
    int mp = idx % MP;
    int n  = idx / MP;
    float p = 0.f;
    if (mp < M) {
        int i = mp / WR, j = mp % WR;
        p = 1.f;
        const float* base = vis + n * HH * WW + (i * GS) * WW + j * GS;
        #pragma unroll
        for (int a = 0; a < GS; a++)
            #pragma unroll
            for (int b = 0; b < GS; b++)
                p *= base[a * WW + b];
    }
    d_vm[idx] = p;
}

// ---------------------------------------------------------------------------
// Persistent-strip tcgen05 GEMM + hinge + reduce (active on "a" targets).
// Grid (29, 1, 4): CTA owns B strip [x*128, x*128+128) with full K resident
// in smem; streams 29 A tiles with cp.async double-buffering; 2 TMEM
// accumulator buffers let epilogue(t-1) overlap MMA(t) and prefetch(t+1).
// Dynamic smem: A0 @0 (64KB), A1 @65536 (64KB), B @131072 (64KB).
// ---------------------------------------------------------------------------
__global__ __launch_bounds__(128, 1) void gemm_tc_kernel() {
#if HAS_TC
    extern __shared__ char dyn_sm[];
    __shared__ uint32_t s_tmem[1];
    __shared__ __align__(8) unsigned long long s_mbar[2];
    __shared__ float s_vm[BN];
    __shared__ float s_red[4];

    const int n   = blockIdx.z;
    const int xs  = blockIdx.x;
    const int tid = threadIdx.x;
    const int wid = tid >> 5, lid = tid & 31;

    uint32_t raw  = smem_u32(dyn_sm);
    uint32_t base = (raw + 1023u) & ~1023u;

    bool leader = false;
    if (wid == 0) {
        asm volatile("tcgen05.alloc.cta_group::1.sync.aligned.shared::cta.b32 [%0], %1;"
                     :: "r"(smem_u32(s_tmem)), "r"(256u) : "memory");
        asm volatile("tcgen05.relinquish_alloc_permit.cta_group::1.sync.aligned;");
        leader = elect_one() != 0;
    }
    if (tid == 0) {
        asm volatile("mbarrier.init.shared.b64 [%0], %1;"
                     :: "r"(smem_u32(&s_mbar[0])), "r"(1u) : "memory");
        asm volatile("mbarrier.init.shared.b64 [%0], %1;"
                     :: "r"(smem_u32(&s_mbar[1])), "r"(1u) : "memory");
    }
    s_vm[tid] = d_vm[n * MP + xs * BN + tid];
    __syncthreads();
    const uint32_t tmem = s_tmem[0];
    const uint32_t mb[2] = { smem_u32(&s_mbar[0]), smem_u32(&s_mbar[1]) };

    const __nv_bfloat16* Abase = d_D1t + (size_t)n * MP * C;
    const __nv_bfloat16* Bg    = d_D2t + ((size_t)n * MP + xs * BN) * C;

    // per-thread load mapping: 32 x 16B vectors; vi = i*128+tid
    // row = vi>>5 (0..127), vec = vi&31 (16B within 512B K-row)
    // smem off = (vec>>3)*16384 + SWZ128(row*128 + (vec&7)*16)

    // prologue: B (resident) + A tile 0 -> buf0
    #pragma unroll
    for (int i = 0; i < 32; i++) {
        int vi = i * 128 + tid;
        int row = vi >> 5, vec = vi & 31;
        uint32_t off = (uint32_t)((vec >> 3) * 16384) + SWZ128((uint32_t)(row * 128 + (vec & 7) * 16));
        cp_async16(base + 131072 + off, Bg + (size_t)row * C + vec * 8);
        cp_async16(base + off,          Abase + (size_t)row * C + vec * 8);
    }

    uint32_t ph[2] = {0u, 0u};
    float local = 0.f;

    #pragma unroll 1
    for (int t = 0; t < NT; t++) {
        const int tb = t & 1;

        // A[t] (and B on t==0) landed?
        cp_async_wait_all();
        asm volatile("fence.proxy.async.shared::cta;" ::: "memory");
        __syncthreads();

        // issue MMA tile t -> tmem[tb]
        if (leader) {
            const uint32_t dt = tmem + tb * 128;
            #pragma unroll
            for (int c = 0; c < 4; c++) {
                uint64_t ad = make_desc(base + tb * 65536 + c * 16384);
                uint64_t bd = make_desc(base + 131072 + c * 16384);
                #pragma unroll
                for (int ks = 0; ks < 4; ks++)
                    mma_f16_ss_cg1(dt, ad + ks * 2, bd + ks * 2, MMA_IDESC,
                                   (uint32_t)(c * 4 + ks)); // first of tile overwrites
            }
            asm volatile(
                "tcgen05.commit.cta_group::1.mbarrier::arrive::one.shared::cluster.b64 [%0];"
                :: "r"(mb[tb]) : "memory");
        }

        if (t > 0) {
            const int pb = (t - 1) & 1;
            // wait MMA t-1 complete (frees buf[pb] and tmem[pb])
            mbar_wait(mb[pb], ph[pb]);
            ph[pb] ^= 1u;

            // prefetch A[t+1] into buf[pb] (overlaps MMA t + epilogue below)
            if (t + 1 < NT) {
                const __nv_bfloat16* An = Abase + (size_t)(t + 1) * BM * C;
                #pragma unroll
                for (int i = 0; i < 32; i++) {
                    int vi = i * 128 + tid;
                    int row = vi >> 5, vec = vi & 31;
                    uint32_t off = (uint32_t)((vec >> 3) * 16384)
                                 + SWZ128((uint32_t)(row * 128 + (vec & 7) * 16));
                    cp_async16(base + pb * 65536 + off, An + (size_t)row * C + vec * 8);
                }
            }

            // epilogue tile t-1 (overlaps MMA t)
            asm volatile("tcgen05.fence::after_thread_sync;" ::: "memory");
            const uint32_t tsrc = tmem + pb * 128;
            #pragma unroll 1
            for (int cb = 0; cb < 4; cb++) {
                uint32_t dr[32];
                asm volatile(
                    "tcgen05.ld.sync.aligned.32x32b.x32.b32 "
                    "{%0, %1, %2, %3, %4, %5, %6, %7, "
                    " %8, %9, %10, %11, %12, %13, %14, %15, "
                    " %16, %17, %18, %19, %20, %21, %22, %23, "
                    " %24, %25, %26, %27, %28, %29, %30, %31}, [%32];"
                    : "=r"(dr[0]),  "=r"(dr[1]),  "=r"(dr[2]),  "=r"(dr[3]),
                      "=r"(dr[4]),  "=r"(dr[5]),  "=r"(dr[6]),  "=r"(dr[7]),
                      "=r"(dr[8]),  "=r"(dr[9]),  "=r"(dr[10]), "=r"(dr[11]),
                      "=r"(dr[12]), "=r"(dr[13]), "=r"(dr[14]), "=r"(dr[15]),
                      "=r"(dr[16]), "=r"(dr[17]), "=r"(dr[18]), "=r"(dr[19]),
                      "=r"(dr[20]), "=r"(dr[21]), "=r"(dr[22]), "=r"(dr[23]),
                      "=r"(dr[24]), "=r"(dr[25]), "=r"(dr[26]), "=r"(dr[27]),
                      "=r"(dr[28]), "=r"(dr[29]), "=r"(dr[30]), "=r"(dr[31])
                    : "r"(tsrc + cb * 32));
                asm volatile("tcgen05.wait::ld.sync.aligned;" ::: "memory");
                #pragma unroll
                for (int j = 0; j < 32; j++)
                    local += s_vm[cb * 32 + j] * fmaxf(__uint_as_float(dr[j]) - 0.2f, 0.f);
            }
            asm volatile("tcgen05.fence::before_thread_sync;" ::: "memory");
        } else if (NT > 1) {
            // t == 0: prefetch A[1] into buf1 (buf1 untouched so far)
            const __nv_bfloat16* An = Abase + (size_t)BM * C;
            #pragma unroll
            for (int i = 0; i < 32; i++) {
                int vi = i * 128 + tid;
                int row = vi >> 5, vec = vi & 31;
                uint32_t off = (uint32_t)((vec >> 3) * 16384)
                             + SWZ128((uint32_t)(row * 128 + (vec & 7) * 16));
                cp_async16(base + 65536 + off, An + (size_t)row * C + vec * 8);
            }
        }
    }

    // tail epilogue: tile NT-1
    {
        const int pb = (NT - 1) & 1;
        mbar_wait(mb[pb], ph[pb]);
        asm volatile("tcgen05.fence::after_thread_sync;" ::: "memory");
        const uint32_t tsrc = tmem + pb * 128;
        #pragma unroll 1
        for (int cb = 0; cb < 4; cb++) {
            uint32_t dr[32];
            asm volatile(
                "tcgen05.ld.sync.aligned.32x32b.x32.b32 "
                "{%0, %1, %2, %3, %4, %5, %6, %7, "
                " %8, %9, %10, %11, %12, %13, %14, %15, "
                " %16, %17, %18, %19, %20, %21, %22, %23, "
                " %24, %25, %26, %27, %28, %29, %30, %31}, [%32];"
                : "=r"(dr[0]),  "=r"(dr[1]),  "=r"(dr[2]),  "=r"(dr[3]),
                  "=r"(dr[4]),  "=r"(dr[5]),  "=r"(dr[6]),  "=r"(dr[7]),
                  "=r"(dr[8]),  "=r"(dr[9]),  "=r"(dr[10]), "=r"(dr[11]),
                  "=r"(dr[12]), "=r"(dr[13]), "=r"(dr[14]), "=r"(dr[15]),
                  "=r"(dr[16]), "=r"(dr[17]), "=r"(dr[18]), "=r"(dr[19]),
                  "=r"(dr[20]), "=r"(dr[21]), "=r"(dr[22]), "=r"(dr[23]),
                  "=r"(dr[24]), "=r"(dr[25]), "=r"(dr[26]), "=r"(dr[27]),
                  "=r"(dr[28]), "=r"(dr[29]), "=r"(dr[30]), "=r"(dr[31])
                : "r"(tsrc + cb * 32));
            asm volatile("tcgen05.wait::ld.sync.aligned;" ::: "memory");
            #pragma unroll
            for (int j = 0; j < 32; j++)
                local += s_vm[cb * 32 + j] * fmaxf(__uint_as_float(dr[j]) - 0.2f, 0.f);
        }
    }

    #pragma unroll
    for (int o = 16; o > 0; o >>= 1)
        local += __shfl_down_sync(0xffffffffu, local, o);
    if (lid == 0) s_red[wid] = local;
    __syncthreads();
    if (tid == 0)
        d_partA[n * GB + xs] = s_red[0] + s_red[1] + s_red[2] + s_red[3];

    if (wid == 0) {
        asm volatile("tcgen05.dealloc.cta_group::1.sync.aligned.b32 %0, %1;"
                     :: "r"(tmem), "r"(256u));
    }
#endif
}

// ---------------------------------------------------------------------------
// Fallback SIMT fp32 GEMM (active only WITHOUT tcgen05). Round-1 tiling.
// ---------------------------------------------------------------------------
__global__ __launch_bounds__(256, 2) void gemm_simt_kernel() {
#if !HAS_TC
    int n = blockIdx.z;
    const float* Ab = d_D1p + n * C * MP + blockIdx.y * BM;
    const float* Bb = d_D2p + n * C * MP + blockIdx.x * BN;

    __shared__ float As[2][BK][BM];
    __shared__ float Bs[2][BK][BN];

    int tid  = threadIdx.x;
    int tx   = tid & 15;
    int ty   = tid >> 4;
    int lrow = tid >> 5;
    int lcol = (tid & 31) << 2;

    float acc[8][8];
    #pragma unroll
    for (int i = 0; i < 8; i++)
        #pragma unroll
        for (int j = 0; j < 8; j++) acc[i][j] = 0.f;

    *(float4*)&As[0][lrow][lcol] = *(const float4*)&Ab[lrow * MP + lcol];
    *(float4*)&Bs[0][lrow][lcol] = *(const float4*)&Bb[lrow * MP + lcol];
    __syncthreads();

    #pragma unroll 1
    for (int k0 = 0; k0 < C; k0 += BK) {
        int buf = (k0 >> 3) & 1;
        if (k0 + BK < C) {
            *(float4*)&As[buf ^ 1][lrow][lcol] =
                *(const float4*)&Ab[(k0 + BK + lrow) * MP + lcol];
            *(float4*)&Bs[buf ^ 1][lrow][lcol] =
                *(const float4*)&Bb[(k0 + BK + lrow) * MP + lcol];
        }
        #pragma unroll
        for (int kk = 0; kk < BK; kk++) {
            float a[8], b[8];
            *(float4*)&a[0] = *(const float4*)&As[buf][kk][ty * 8];
            *(float4*)&a[4] = *(const float4*)&As[buf][kk][ty * 8 + 4];
            *(float4*)&b[0] = *(const float4*)&Bs[buf][kk][tx * 8];
            *(float4*)&b[4] = *(const float4*)&Bs[buf][kk][tx * 8 + 4];
            #pragma unroll
            for (int i = 0; i < 8; i++)
                #pragma unroll
                for (int j = 0; j < 8; j++)
                    acc[i][j] = fmaf(a[i], b[j], acc[i][j]);
        }
        __syncthreads();
    }

    float vmv[8];
    #pragma unroll
    for (int j = 0; j < 8; j++)
        vmv[j] = d_vm[n * MP + blockIdx.x * BN + tx * 8 + j];

    float local = 0.f;
    #pragma unroll
    for (int i = 0; i < 8; i++)
        #pragma unroll
        for (int j = 0; j < 8; j++)
            local += vmv[j] * fmaxf(acc[i][j] - 0.2f, 0.f);

    #pragma unroll
    for (int o = 16; o > 0; o >>= 1)
        local += __shfl_down_sync(0xffffffffu, local, o);

    __shared__ float wsum[8];
    if ((tid & 31) == 0) wsum[tid >> 5] = local;
    __syncthreads();
    if (tid == 0) {
        float t = 0.f;
        #pragma unroll
        for (int w = 0; w < 8; w++) t += wsum[w];
        d_partA[(blockIdx.z * GB + blockIdx.y) * GB + blockIdx.x] = t;
    }
#endif
}

// ---------------------------------------------------------------------------
// Positive-pair correction (coalesced bf16 dots on transposed arrays).
// ---------------------------------------------------------------------------
__device__ __forceinline__ float dot8(uint4 a, uint4 b) {
    const __nv_bfloat162* pa = (const __nv_bfloat162*)&a;
    const __nv_bfloat162* pb = (const __nv_bfloat162*)&b;
    float s = 0.f;
    #pragma unroll
    for (int k = 0; k < 4; k++) {
        float2 fa = __bfloat1622float2(pa[k]);
        float2 fb = __bfloat1622float2(pb[k]);
        s += fa.x * fb.x + fa.y * fb.y;
    }
    return s;
}

__global__ void pos_kernel(const float* __restrict__ homo) {
    int warp = threadIdx.x >> 5;
    int lane = threadIdx.x & 31;
    int item = blockIdx.x * 8 + warp;   // 0 .. 14399
    float contrib = 0.f;

    if (item < NB * M) {
        int n  = item / M;
        int ij = item % M;
        int i  = ij / WR, j = ij % WR;
        float x = j * 8 + 4.f, y = i * 8 + 4.f;
        const float* Hm = homo + n * 9;
        float wxh = Hm[0] * x + Hm[1] * y + Hm[2];
        float wyh = Hm[3] * x + Hm[4] * y + Hm[5];
        float wzh = Hm[6] * x + Hm[7] * y + Hm[8];
        float wx = wxh / wzh, wy = wyh / wzh;
        float vmv = d_vm[n * MP + ij];

        const uint4 bvec = ((const uint4*)(d_D2t + ((size_t)n * MP + ij) * C))[lane];

        int hs = (int)floorf((wy - 11.5f) * 0.125f);
        int ws = (int)floorf((wx - 11.5f) * 0.125f);
        for (int hh = hs; hh < hs + 4; hh++) {
            if (hh < 0 || hh >= HR) continue;
            float dy = hh * 8 + 4.f - wy;
            for (int wc = ws; wc < ws + 4; wc++) {
                if (wc < 0 || wc >= WR) continue;
                float dx = wc * 8 + 4.f - wx;
                if (dx * dx + dy * dy <= 56.25f) {   // dist <= 7.5
                    const uint4 avec =
                        ((const uint4*)(d_D1t + ((size_t)n * MP + hh * WR + wc) * C))[lane];
                    float dt = dot8(avec, bvec);
                    #pragma unroll
                    for (int o = 16; o > 0; o >>= 1)
                        dt += __shfl_down_sync(0xffffffffu, dt, o);
                    dt = __shfl_sync(0xffffffffu, dt, 0);
                    if (lane == 0)
                        contrib += vmv * (fmaxf(1.f - dt, 0.f) - fmaxf(dt - 0.2f, 0.f));
                }
            }
        }
    }

    __shared__ float wsh[8];
    if (lane == 0) wsh[warp] = contrib;
    __syncthreads();
    if (threadIdx.x == 0) {
        float t = 0.f;
        #pragma unroll
        for (int w = 0; w < 8; w++) t += wsh[w];
        d_partB[blockIdx.x] = t;
    }
}

// ---------------------------------------------------------------------------
// Final deterministic reduction. partA bound matches the active GEMM path.
// ---------------------------------------------------------------------------
__global__ void final_kernel(float* __restrict__ out) {
    __shared__ float sh[256];
    int tid = threadIdx.x;

#if HAS_TC
    const int NPA = NB * GB;        // 116 strip partials
#else
    const int NPA = GB * GB * NB;   // 3364 tile partials
#endif

    float s = 0.f;
    for (int k = tid; k < NPA; k += 256) s += d_partA[k];
    for (int k = tid; k < NPOSB; k += 256) s += d_partB[k];
    float v = 0.f;
    for (int k = tid; k < NB * MP; k += 256) v += d_vm[k];  // pads are 0

    sh[tid] = s;
    __syncthreads();
    for (int o = 128; o > 0; o >>= 1) {
        if (tid < o) sh[tid] += sh[tid + o];
        __syncthreads();
    }
    float total = sh[0];
    __syncthreads();

    sh[tid] = v;
    __syncthreads();
    for (int o = 128; o > 0; o >>= 1) {
        if (tid < o) sh[tid] += sh[tid + o];
        __syncthreads();
    }
    if (tid == 0)
        out[0] = total / (3600.f * sh[0]);   // LOSS_LAMBDA = 1
}

// ---------------------------------------------------------------------------
extern "C" void kernel_launch(void* const* d_in, const int* in_sizes, int n_in,
                              void* d_out, int out_size) {
    const float* desc1 = nullptr;
    const float* desc2 = nullptr;
    const float* homo  = nullptr;
    const float* vis   = nullptr;
    for (int k = 0; k < n_in; k++) {
        if (in_sizes[k] == NB * C * M) {
            if (!desc1) desc1 = (const float*)d_in[k];
            else if (!desc2) desc2 = (const float*)d_in[k];
        } else if (in_sizes[k] == NB * 9) {
            homo = (const float*)d_in[k];
        } else if (in_sizes[k] == NB * HH * WW) {
            vis = (const float*)d_in[k];
        }
    }

    // Idempotent, capture-safe.
    cudaFuncSetAttribute(gemm_tc_kernel,
                         cudaFuncAttributeMaxDynamicSharedMemorySize, 197632);

    transpose_kernel<<<dim3(116, 8, NB), dim3(32, 8)>>>(desc1, desc2);
    vm_kernel<<<(NB * MP + 255) / 256, 256>>>(vis);
    pad_kernel<<<(NB * C * MP + 255) / 256, 256>>>(desc1, desc2);   // no-op on "a"
    gemm_tc_kernel<<<dim3(GB, 1, NB), 128, 197632>>>();             // active on "a"
    gemm_simt_kernel<<<dim3(GB, GB, NB), 256>>>();                  // active otherwise
    pos_kernel<<<NPOSB, 256>>>(homo);
    final_kernel<<<1, 256>>>((float*)d_out);
}

// round 6
// speedup vs baseline: 8.8463x; 1.0985x over previous
#include <cuda_runtime.h>
#include <cuda_bf16.h>
#include <cstdint>

// ---------------------------------------------------------------------------
// Arch feature gate: tcgen05/TMEM are "a"-target-only. Non-"a" passes compile
// the SIMT fallback instead; exactly one GEMM kernel is active per pass.
// ---------------------------------------------------------------------------
#if defined(__CUDA_ARCH__) && (defined(__CUDA_ARCH_FEAT_SM103_ALL) || defined(__CUDA_ARCH_FEAT_SM100_ALL))
#define HAS_TC 1
#else
#define HAS_TC 0
#endif

// Problem constants
#define NB 4
#define C  256
#define HR 60
#define WR 60
#define M  3600          // HR*WR
#define MP 3712          // padded to 29*128
#define GS 8
#define HH 480
#define WW 480

#define BM 128
#define BN 128
#define BK 8
#define GB 29            // tiles per GEMM dim
#define NT 29            // A tiles per strip (persistent loop)
#define NPOSB 1800

// idesc kind::f16: dtype=F32(1<<4), atype=BF16(1<<7), btype=BF16(1<<10),
// N/8 << 17, M/16 << 24  ->  M=128, N=128
#define MMA_IDESC 0x8200490u

// __device__ scratch (no allocation allowed)
__device__ __align__(16) __nv_bfloat16 d_D1t[(size_t)NB * MP * C];  // [n][m][c] bf16
__device__ __align__(16) __nv_bfloat16 d_D2t[(size_t)NB * MP * C];
__device__ float d_D1p[NB * C * MP];                                // fp32 fallback
__device__ float d_D2p[NB * C * MP];
__device__ float d_vm[NB * MP];
__device__ float d_partA[GB * GB * NB];
__device__ float d_partB[NPOSB];

// ---------------------------------------------------------------------------
// Helpers
// ---------------------------------------------------------------------------
__device__ __forceinline__ uint32_t smem_u32(const void* p) {
    uint32_t a;
    asm("{ .reg .u64 t; cvta.to.shared.u64 t, %1; cvt.u32.u64 %0, t; }" : "=r"(a) : "l"(p));
    return a;
}
#define SWZ128(off) ((off) ^ (((off) >> 3) & 0x70))

__device__ __forceinline__ void cp_async16(uint32_t dst, const void* src) {
    asm volatile("cp.async.cg.shared.global [%0], [%1], 16;"
                 :: "r"(dst), "l"(src) : "memory");
}
__device__ __forceinline__ void cp_async_wait_all() {
    asm volatile("cp.async.wait_all;" ::: "memory");
}

#if HAS_TC
__device__ __forceinline__ uint32_t elect_one() {
    uint32_t p;
    asm volatile("{ .reg .pred p; elect.sync _|p, 0xFFFFFFFF; selp.b32 %0, 1, 0, p; }" : "=r"(p));
    return p;
}
static __device__ __forceinline__ uint64_t make_desc(uint32_t addr) {
    // SW128, version=1(Blackwell), SBO=64, LBO=1
    const uint64_t base = (uint64_t(2) << 61) | (uint64_t(1) << 46)
                        | (uint64_t(64) << 32) | (uint64_t(1) << 16);
    return base | ((uint64_t)(addr >> 4) & 0x3FFF);
}
__device__ __forceinline__ void mma_f16_ss_cg1(uint32_t d_tmem, uint64_t a_desc,
                                               uint64_t b_desc, uint32_t idesc,
                                               uint32_t enable) {
    asm volatile(
        "{\n\t.reg .pred p;\n\t"
        "setp.ne.u32 p, %4, 0;\n\t"
        "tcgen05.mma.cta_group::1.kind::f16 [%0], %1, %2, %3, {%5, %5, %5, %5}, p;\n\t}"
        :: "r"(d_tmem), "l"(a_desc), "l"(b_desc), "r"(idesc), "r"(enable), "r"(0u)
        : "memory");
}
__device__ __forceinline__ void mbar_wait(uint32_t mbar, uint32_t parity) {
    uint32_t done;
    asm volatile(
        "{\n\t.reg .pred p;\n\t"
        "mbarrier.try_wait.parity.acquire.cta.shared::cta.b64 p, [%1], %2;\n\t"
        "selp.b32 %0, 1, 0, p;\n\t}"
        : "=r"(done) : "r"(mbar), "r"(parity) : "memory");
    if (!done) {
        asm volatile(
            "{\n\t.reg .pred P1;\n\t"
            "WL_%=:\n\t"
            "mbarrier.try_wait.parity.acquire.cta.shared::cta.b64 P1, [%0], %1, 0x989680;\n\t"
            "@P1 bra.uni WD_%=;\n\t"
            "bra.uni WL_%=;\n\t"
            "WD_%=:\n\t}"
            :: "r"(mbar), "r"(parity) : "memory");
    }
}

#define LDTM_X32(dr, addr)                                                     \
    asm volatile(                                                              \
        "tcgen05.ld.sync.aligned.32x32b.x32.b32 "                              \
        "{%0, %1, %2, %3, %4, %5, %6, %7, "                                    \
        " %8, %9, %10, %11, %12, %13, %14, %15, "                              \
        " %16, %17, %18, %19, %20, %21, %22, %23, "                            \
        " %24, %25, %26, %27, %28, %29, %30, %31}, [%32];"                     \
        : "=r"((dr)[0]),  "=r"((dr)[1]),  "=r"((dr)[2]),  "=r"((dr)[3]),       \
          "=r"((dr)[4]),  "=r"((dr)[5]),  "=r"((dr)[6]),  "=r"((dr)[7]),       \
          "=r"((dr)[8]),  "=r"((dr)[9]),  "=r"((dr)[10]), "=r"((dr)[11]),      \
          "=r"((dr)[12]), "=r"((dr)[13]), "=r"((dr)[14]), "=r"((dr)[15]),      \
          "=r"((dr)[16]), "=r"((dr)[17]), "=r"((dr)[18]), "=r"((dr)[19]),      \
          "=r"((dr)[20]), "=r"((dr)[21]), "=r"((dr)[22]), "=r"((dr)[23]),      \
          "=r"((dr)[24]), "=r"((dr)[25]), "=r"((dr)[26]), "=r"((dr)[27]),      \
          "=r"((dr)[28]), "=r"((dr)[29]), "=r"((dr)[30]), "=r"((dr)[31])       \
        : "r"(addr))

// Epilogue for one tile: this warp reads 64 columns [c0, c0+64) of its
// 32-lane subpartition; two LDTMs, ONE wait, 4-way FMA accumulation.
__device__ __forceinline__ void epi64(uint32_t tsrc, const float* vmv, float& local) {
    uint32_t dr[64];
    LDTM_X32(dr,      tsrc);
    LDTM_X32(dr + 32, tsrc + 32);
    asm volatile("tcgen05.wait::ld.sync.aligned;" ::: "memory");
    float a0 = 0.f, a1 = 0.f, a2 = 0.f, a3 = 0.f;
    #pragma unroll
    for (int k = 0; k < 64; k += 4) {
        a0 = fmaf(vmv[k + 0], fmaxf(__uint_as_float(dr[k + 0]) - 0.2f, 0.f), a0);
        a1 = fmaf(vmv[k + 1], fmaxf(__uint_as_float(dr[k + 1]) - 0.2f, 0.f), a1);
        a2 = fmaf(vmv[k + 2], fmaxf(__uint_as_float(dr[k + 2]) - 0.2f, 0.f), a2);
        a3 = fmaf(vmv[k + 3], fmaxf(__uint_as_float(dr[k + 3]) - 0.2f, 0.f), a3);
    }
    local += (a0 + a1) + (a2 + a3);
}
#endif

// ---------------------------------------------------------------------------
// Transpose + pad + bf16 convert: [n][c][m] f32 -> [n][m][c] bf16
// ---------------------------------------------------------------------------
__global__ void transpose_kernel(const float* __restrict__ d1,
                                 const float* __restrict__ d2) {
    __shared__ float t1[32][33];
    __shared__ float t2[32][33];
    int m0 = blockIdx.x * 32, c0 = blockIdx.y * 32, n = blockIdx.z;
    int tx = threadIdx.x, ty = threadIdx.y;   // 32 x 8

    #pragma unroll
    for (int i = 0; i < 4; i++) {
        int c = c0 + ty + i * 8, m = m0 + tx;
        float v1 = 0.f, v2 = 0.f;
        if (m < M) {
            size_t idx = ((size_t)n * C + c) * M + m;
            v1 = d1[idx]; v2 = d2[idx];
        }
        t1[ty + i * 8][tx] = v1;
        t2[ty + i * 8][tx] = v2;
    }
    __syncthreads();
    #pragma unroll
    for (int i = 0; i < 4; i++) {
        int m = m0 + ty + i * 8, c = c0 + tx;
        if (m < MP) {
            size_t o = ((size_t)n * MP + m) * C + c;
            d_D1t[o] = __float2bfloat16(t1[tx][ty + i * 8]);
            d_D2t[o] = __float2bfloat16(t2[tx][ty + i * 8]);
        }
    }
}

// ---------------------------------------------------------------------------
// Fallback prep (no-op on "a" targets)
// ---------------------------------------------------------------------------
__global__ void pad_kernel(const float* __restrict__ d1, const float* __restrict__ d2) {
#if !HAS_TC
    int idx = blockIdx.x * blockDim.x + threadIdx.x;
    if (idx >= NB * C * MP) return;
    int mp = idx % MP;
    int nc = idx / MP;
    float v1 = 0.f, v2 = 0.f;
    if (mp < M) {
        int s = nc * M + mp;
        v1 = d1[s];
        v2 = d2[s];
    }
    d_D1p[idx] = v1;
    d_D2p[idx] = v2;
#endif
}

// ---------------------------------------------------------------------------
// vm[n, i, j] = prod of 8x8 block of vis_mask1; padded entries are 0.
// ---------------------------------------------------------------------------
__global__ void vm_kernel(const float* __restrict__ vis) {
    int idx = blockIdx.x * blockDim.x + threadIdx.x;
    if (idx >= NB * MP) return;
    int mp = idx % MP;
    int n  = idx / MP;
    float p = 0.f;
    if (mp < M) {
        int i = mp / WR, j = mp % WR;
        p = 1.f;
        const float* base = vis + n * HH * WW + (i * GS) * WW + j * GS;
        #pragma unroll
        for (int a = 0; a < GS; a++)
            #pragma unroll
            for (int b = 0; b < GS; b++)
                p *= base[a * WW + b];
    }
    d_vm[idx] = p;
}

// ---------------------------------------------------------------------------
// Persistent-strip tcgen05 GEMM + hinge + reduce (active on "a" targets).
// Grid (29, 1, 4), 256 threads. CTA owns B strip with full K resident in
// smem; streams 29 A tiles (cp.async double-buffer); 2 TMEM accumulators so
// epilogue(t-1) + prefetch(t+1) overlap MMA(t). Epilogue is column-split
// across 8 warps (warps 0-3: cols 0-63, warps 4-7: cols 64-127), vm held in
// registers, one wait::ld per tile per warp.
// Dynamic smem: A0 @0 (64KB), A1 @65536 (64KB), B @131072 (64KB).
// ---------------------------------------------------------------------------
__global__ __launch_bounds__(256, 1) void gemm_tc_kernel() {
#if HAS_TC
    extern __shared__ char dyn_sm[];
    __shared__ uint32_t s_tmem[1];
    __shared__ __align__(8) unsigned long long s_mbar[2];
    __shared__ float s_red[8];

    const int n   = blockIdx.z;
    const int xs  = blockIdx.x;
    const int tid = threadIdx.x;
    const int wid = tid >> 5, lid = tid & 31;

    uint32_t raw  = smem_u32(dyn_sm);
    uint32_t base = (raw + 1023u) & ~1023u;

    bool leader = false;
    if (wid == 0) {
        asm volatile("tcgen05.alloc.cta_group::1.sync.aligned.shared::cta.b32 [%0], %1;"
                     :: "r"(smem_u32(s_tmem)), "r"(256u) : "memory");
        asm volatile("tcgen05.relinquish_alloc_permit.cta_group::1.sync.aligned;");
        leader = elect_one() != 0;
    }
    if (tid == 0) {
        asm volatile("mbarrier.init.shared.b64 [%0], %1;"
                     :: "r"(smem_u32(&s_mbar[0])), "r"(1u) : "memory");
        asm volatile("mbarrier.init.shared.b64 [%0], %1;"
                     :: "r"(smem_u32(&s_mbar[1])), "r"(1u) : "memory");
    }

    // per-thread vm columns (constant across all 29 tiles): 64 registers
    const int c0 = (wid >= 4) ? 64 : 0;
    float vmv[64];
    {
        const float* vmb = d_vm + n * MP + xs * BN + c0;
        #pragma unroll
        for (int k = 0; k < 64; k++) vmv[k] = vmb[k];
    }
    __syncthreads();
    const uint32_t tmem = s_tmem[0];
    const uint32_t mb[2] = { smem_u32(&s_mbar[0]), smem_u32(&s_mbar[1]) };

    const __nv_bfloat16* Abase = d_D1t + (size_t)n * MP * C;
    const __nv_bfloat16* Bg    = d_D2t + ((size_t)n * MP + xs * BN) * C;

    // load mapping: 4096 16B vectors per 64KB buffer; 16 per thread.
    // vi = i*256+tid; row = vi>>5, vec = vi&31;
    // smem off = (vec>>3)*16384 + SWZ128(row*128 + (vec&7)*16)

    // prologue: B (resident) + A tile 0 -> buf0
    #pragma unroll
    for (int i = 0; i < 16; i++) {
        int vi = i * 256 + tid;
        int row = vi >> 5, vec = vi & 31;
        uint32_t off = (uint32_t)((vec >> 3) * 16384) + SWZ128((uint32_t)(row * 128 + (vec & 7) * 16));
        cp_async16(base + 131072 + off, Bg + (size_t)row * C + vec * 8);
        cp_async16(base + off,          Abase + (size_t)row * C + vec * 8);
    }

    uint32_t ph[2] = {0u, 0u};
    float local = 0.f;

    #pragma unroll 1
    for (int t = 0; t < NT; t++) {
        const int tb = t & 1;

        // A[t] (and B on t==0) landed?
        cp_async_wait_all();
        asm volatile("fence.proxy.async.shared::cta;" ::: "memory");
        __syncthreads();

        // issue MMA tile t -> tmem[tb]
        if (leader) {
            const uint32_t dt = tmem + tb * 128;
            #pragma unroll
            for (int c = 0; c < 4; c++) {
                uint64_t ad = make_desc(base + tb * 65536 + c * 16384);
                uint64_t bd = make_desc(base + 131072 + c * 16384);
                #pragma unroll
                for (int ks = 0; ks < 4; ks++)
                    mma_f16_ss_cg1(dt, ad + ks * 2, bd + ks * 2, MMA_IDESC,
                                   (uint32_t)(c * 4 + ks)); // first of tile overwrites
            }
            asm volatile(
                "tcgen05.commit.cta_group::1.mbarrier::arrive::one.shared::cluster.b64 [%0];"
                :: "r"(mb[tb]) : "memory");
        }

        if (t > 0) {
            const int pb = (t - 1) & 1;
            // wait MMA t-1 complete (frees buf[pb] and tmem[pb])
            mbar_wait(mb[pb], ph[pb]);
            ph[pb] ^= 1u;

            // prefetch A[t+1] into buf[pb] (overlaps MMA t + epilogue below)
            if (t + 1 < NT) {
                const __nv_bfloat16* An = Abase + (size_t)(t + 1) * BM * C;
                #pragma unroll
                for (int i = 0; i < 16; i++) {
                    int vi = i * 256 + tid;
                    int row = vi >> 5, vec = vi & 31;
                    uint32_t off = (uint32_t)((vec >> 3) * 16384)
                                 + SWZ128((uint32_t)(row * 128 + (vec & 7) * 16));
                    cp_async16(base + pb * 65536 + off, An + (size_t)row * C + vec * 8);
                }
            }

            // epilogue tile t-1 (overlaps MMA t)
            asm volatile("tcgen05.fence::after_thread_sync;" ::: "memory");
            epi64(tmem + pb * 128 + c0, vmv, local);
            asm volatile("tcgen05.fence::before_thread_sync;" ::: "memory");
        } else if (NT > 1) {
            // t == 0: prefetch A[1] into buf1
            const __nv_bfloat16* An = Abase + (size_t)BM * C;
            #pragma unroll
            for (int i = 0; i < 16; i++) {
                int vi = i * 256 + tid;
                int row = vi >> 5, vec = vi & 31;
                uint32_t off = (uint32_t)((vec >> 3) * 16384)
                             + SWZ128((uint32_t)(row * 128 + (vec & 7) * 16));
                cp_async16(base + 65536 + off, An + (size_t)row * C + vec * 8);
            }
        }
    }

    // tail epilogue: tile NT-1
    {
        const int pb = (NT - 1) & 1;
        mbar_wait(mb[pb], ph[pb]);
        asm volatile("tcgen05.fence::after_thread_sync;" ::: "memory");
        epi64(tmem + pb * 128 + c0, vmv, local);
    }

    #pragma unroll
    for (int o = 16; o > 0; o >>= 1)
        local += __shfl_down_sync(0xffffffffu, local, o);
    if (lid == 0) s_red[wid] = local;
    __syncthreads();
    if (tid == 0) {
        float t = 0.f;
        #pragma unroll
        for (int w = 0; w < 8; w++) t += s_red[w];
        d_partA[n * GB + xs] = t;
    }

    if (wid == 0) {
        asm volatile("tcgen05.dealloc.cta_group::1.sync.aligned.b32 %0, %1;"
                     :: "r"(tmem), "r"(256u));
    }
#endif
}

// ---------------------------------------------------------------------------
// Fallback SIMT fp32 GEMM (active only WITHOUT tcgen05). Round-1 tiling.
// ---------------------------------------------------------------------------
__global__ __launch_bounds__(256, 2) void gemm_simt_kernel() {
#if !HAS_TC
    int n = blockIdx.z;
    const float* Ab = d_D1p + n * C * MP + blockIdx.y * BM;
    const float* Bb = d_D2p + n * C * MP + blockIdx.x * BN;

    __shared__ float As[2][BK][BM];
    __shared__ float Bs[2][BK][BN];

    int tid  = threadIdx.x;
    int tx   = tid & 15;
    int ty   = tid >> 4;
    int lrow = tid >> 5;
    int lcol = (tid & 31) << 2;

    float acc[8][8];
    #pragma unroll
    for (int i = 0; i < 8; i++)
        #pragma unroll
        for (int j = 0; j < 8; j++) acc[i][j] = 0.f;

    *(float4*)&As[0][lrow][lcol] = *(const float4*)&Ab[lrow * MP + lcol];
    *(float4*)&Bs[0][lrow][lcol] = *(const float4*)&Bb[lrow * MP + lcol];
    __syncthreads();

    #pragma unroll 1
    for (int k0 = 0; k0 < C; k0 += BK) {
        int buf = (k0 >> 3) & 1;
        if (k0 + BK < C) {
            *(float4*)&As[buf ^ 1][lrow][lcol] =
                *(const float4*)&Ab[(k0 + BK + lrow) * MP + lcol];
            *(float4*)&Bs[buf ^ 1][lrow][lcol] =
                *(const float4*)&Bb[(k0 + BK + lrow) * MP + lcol];
        }
        #pragma unroll
        for (int kk = 0; kk < BK; kk++) {
            float a[8], b[8];
            *(float4*)&a[0] = *(const float4*)&As[buf][kk][ty * 8];
            *(float4*)&a[4] = *(const float4*)&As[buf][kk][ty * 8 + 4];
            *(float4*)&b[0] = *(const float4*)&Bs[buf][kk][tx * 8];
            *(float4*)&b[4] = *(const float4*)&Bs[buf][kk][tx * 8 + 4];
            #pragma unroll
            for (int i = 0; i < 8; i++)
                #pragma unroll
                for (int j = 0; j < 8; j++)
                    acc[i][j] = fmaf(a[i], b[j], acc[i][j]);
        }
        __syncthreads();
    }

    float vmv[8];
    #pragma unroll
    for (int j = 0; j < 8; j++)
        vmv[j] = d_vm[n * MP + blockIdx.x * BN + tx * 8 + j];

    float local = 0.f;
    #pragma unroll
    for (int i = 0; i < 8; i++)
        #pragma unroll
        for (int j = 0; j < 8; j++)
            local += vmv[j] * fmaxf(acc[i][j] - 0.2f, 0.f);

    #pragma unroll
    for (int o = 16; o > 0; o >>= 1)
        local += __shfl_down_sync(0xffffffffu, local, o);

    __shared__ float wsum[8];
    if ((tid & 31) == 0) wsum[tid >> 5] = local;
    __syncthreads();
    if (tid == 0) {
        float t = 0.f;
        #pragma unroll
        for (int w = 0; w < 8; w++) t += wsum[w];
        d_partA[(blockIdx.z * GB + blockIdx.y) * GB + blockIdx.x] = t;
    }
#endif
}

// ---------------------------------------------------------------------------
// Positive-pair correction (coalesced bf16 dots on transposed arrays).
// ---------------------------------------------------------------------------
__device__ __forceinline__ float dot8(uint4 a, uint4 b) {
    const __nv_bfloat162* pa = (const __nv_bfloat162*)&a;
    const __nv_bfloat162* pb = (const __nv_bfloat162*)&b;
    float s = 0.f;
    #pragma unroll
    for (int k = 0; k < 4; k++) {
        float2 fa = __bfloat1622float2(pa[k]);
        float2 fb = __bfloat1622float2(pb[k]);
        s += fa.x * fb.x + fa.y * fb.y;
    }
    return s;
}

__global__ void pos_kernel(const float* __restrict__ homo) {
    int warp = threadIdx.x >> 5;
    int lane = threadIdx.x & 31;
    int item = blockIdx.x * 8 + warp;   // 0 .. 14399
    float contrib = 0.f;

    if (item < NB * M) {
        int n  = item / M;
        int ij = item % M;
        int i  = ij / WR, j = ij % WR;
        float x = j * 8 + 4.f, y = i * 8 + 4.f;
        const float* Hm = homo + n * 9;
        float wxh = Hm[0] * x + Hm[1] * y + Hm[2];
        float wyh = Hm[3] * x + Hm[4] * y + Hm[5];
        float wzh = Hm[6] * x + Hm[7] * y + Hm[8];
        float wx = wxh / wzh, wy = wyh / wzh;
        float vmv = d_vm[n * MP + ij];

        const uint4 bvec = ((const uint4*)(d_D2t + ((size_t)n * MP + ij) * C))[lane];

        int hs = (int)floorf((wy - 11.5f) * 0.125f);
        int ws = (int)floorf((wx - 11.5f) * 0.125f);
        for (int hh = hs; hh < hs + 4; hh++) {
            if (hh < 0 || hh >= HR) continue;
            float dy = hh * 8 + 4.f - wy;
            for (int wc = ws; wc < ws + 4; wc++) {
                if (wc < 0 || wc >= WR) continue;
                float dx = wc * 8 + 4.f - wx;
                if (dx * dx + dy * dy <= 56.25f) {   // dist <= 7.5
                    const uint4 avec =
                        ((const uint4*)(d_D1t + ((size_t)n * MP + hh * WR + wc) * C))[lane];
                    float dt = dot8(avec, bvec);
                    #pragma unroll
                    for (int o = 16; o > 0; o >>= 1)
                        dt += __shfl_down_sync(0xffffffffu, dt, o);
                    dt = __shfl_sync(0xffffffffu, dt, 0);
                    if (lane == 0)
                        contrib += vmv * (fmaxf(1.f - dt, 0.f) - fmaxf(dt - 0.2f, 0.f));
                }
            }
        }
    }

    __shared__ float wsh[8];
    if (lane == 0) wsh[warp] = contrib;
    __syncthreads();
    if (threadIdx.x == 0) {
        float t = 0.f;
        #pragma unroll
        for (int w = 0; w < 8; w++) t += wsh[w];
        d_partB[blockIdx.x] = t;
    }
}

// ---------------------------------------------------------------------------
// Final deterministic reduction. partA bound matches the active GEMM path.
// ---------------------------------------------------------------------------
__global__ void final_kernel(float* __restrict__ out) {
    __shared__ float sh[256];
    int tid = threadIdx.x;

#if HAS_TC
    const int NPA = NB * GB;        // 116 strip partials
#else
    const int NPA = GB * GB * NB;   // 3364 tile partials
#endif

    float s = 0.f;
    for (int k = tid; k < NPA; k += 256) s += d_partA[k];
    for (int k = tid; k < NPOSB; k += 256) s += d_partB[k];
    float v = 0.f;
    for (int k = tid; k < NB * MP; k += 256) v += d_vm[k];  // pads are 0

    sh[tid] = s;
    __syncthreads();
    for (int o = 128; o > 0; o >>= 1) {
        if (tid < o) sh[tid] += sh[tid + o];
        __syncthreads();
    }
    float total = sh[0];
    __syncthreads();

    sh[tid] = v;
    __syncthreads();
    for (int o = 128; o > 0; o >>= 1) {
        if (tid < o) sh[tid] += sh[tid + o];
        __syncthreads();
    }
    if (tid == 0)
        out[0] = total / (3600.f * sh[0]);   // LOSS_LAMBDA = 1
}

// ---------------------------------------------------------------------------
extern "C" void kernel_launch(void* const* d_in, const int* in_sizes, int n_in,
                              void* d_out, int out_size) {
    const float* desc1 = nullptr;
    const float* desc2 = nullptr;
    const float* homo  = nullptr;
    const float* vis   = nullptr;
    for (int k = 0; k < n_in; k++) {
        if (in_sizes[k] == NB * C * M) {
            if (!desc1) desc1 = (const float*)d_in[k];
            else if (!desc2) desc2 = (const float*)d_in[k];
        } else if (in_sizes[k] == NB * 9) {
            homo = (const float*)d_in[k];
        } else if (in_sizes[k] == NB * HH * WW) {
            vis = (const float*)d_in[k];
        }
    }

    // Idempotent, capture-safe.
    cudaFuncSetAttribute(gemm_tc_kernel,
                         cudaFuncAttributeMaxDynamicSharedMemorySize, 197632);

    transpose_kernel<<<dim3(116, 8, NB), dim3(32, 8)>>>(desc1, desc2);
    vm_kernel<<<(NB * MP + 255) / 256, 256>>>(vis);
    pad_kernel<<<(NB * C * MP + 255) / 256, 256>>>(desc1, desc2);   // no-op on "a"
    gemm_tc_kernel<<<dim3(GB, 1, NB), 256, 197632>>>();             // active on "a"
    gemm_simt_kernel<<<dim3(GB, GB, NB), 256>>>();                  // active otherwise
    pos_kernel<<<NPOSB, 256>>>(homo);
    final_kernel<<<1, 256>>>((float*)d_out);
}

// round 7
// speedup vs baseline: 9.7113x; 1.0978x over previous
#include <cuda_runtime.h>
#include <cuda_bf16.h>
#include <cstdint>

// ---------------------------------------------------------------------------
// Arch feature gate: tcgen05/TMEM are "a"-target-only. Non-"a" passes compile
// the SIMT fallback instead; exactly one GEMM kernel is active per pass.
// ---------------------------------------------------------------------------
#if defined(__CUDA_ARCH__) && (defined(__CUDA_ARCH_FEAT_SM103_ALL) || defined(__CUDA_ARCH_FEAT_SM100_ALL))
#define HAS_TC 1
#else
#define HAS_TC 0
#endif

// Problem constants
#define NB 4
#define C  256
#define HR 60
#define WR 60
#define M  3600          // HR*WR
#define MP 3712          // padded to 29*128
#define GS 8
#define HH 480
#define WW 480

#define BM 128
#define BN 128
#define BK 8
#define GB 29            // tiles per GEMM dim
#define NT 29            // A tiles per strip (persistent loop)
#define NPOSB 1800

// idesc kind::f16: dtype=F32(1<<4), atype=BF16(1<<7), btype=BF16(1<<10),
// N/8 << 17, M/16 << 24  ->  M=128, N=128
#define MMA_IDESC 0x8200490u

// __device__ scratch (no allocation allowed)
__device__ __align__(16) __nv_bfloat16 d_D1t[(size_t)NB * MP * C];  // [n][m][c] bf16
__device__ __align__(16) __nv_bfloat16 d_D2t[(size_t)NB * MP * C];
__device__ float d_D1p[NB * C * MP];                                // fp32 fallback
__device__ float d_D2p[NB * C * MP];
__device__ float d_vm[NB * MP];
__device__ float d_partA[GB * GB * NB];
__device__ float d_partB[NPOSB];

// ---------------------------------------------------------------------------
// Helpers
// ---------------------------------------------------------------------------
__device__ __forceinline__ uint32_t smem_u32(const void* p) {
    uint32_t a;
    asm("{ .reg .u64 t; cvta.to.shared.u64 t, %1; cvt.u32.u64 %0, t; }" : "=r"(a) : "l"(p));
    return a;
}
#define SWZ128(off) ((off) ^ (((off) >> 3) & 0x70))

__device__ __forceinline__ void cp_async16(uint32_t dst, const void* src) {
    asm volatile("cp.async.cg.shared.global [%0], [%1], 16;"
                 :: "r"(dst), "l"(src) : "memory");
}

#if HAS_TC
__device__ __forceinline__ uint32_t elect_one() {
    uint32_t p;
    asm volatile("{ .reg .pred p; elect.sync _|p, 0xFFFFFFFF; selp.b32 %0, 1, 0, p; }" : "=r"(p));
    return p;
}
static __device__ __forceinline__ uint64_t make_desc(uint32_t addr) {
    // SW128, version=1(Blackwell), SBO=64, LBO=1
    const uint64_t base = (uint64_t(2) << 61) | (uint64_t(1) << 46)
                        | (uint64_t(64) << 32) | (uint64_t(1) << 16);
    return base | ((uint64_t)(addr >> 4) & 0x3FFF);
}
__device__ __forceinline__ void mma_f16_ss_cg1(uint32_t d_tmem, uint64_t a_desc,
                                               uint64_t b_desc, uint32_t idesc,
                                               uint32_t enable) {
    asm volatile(
        "{\n\t.reg .pred p;\n\t"
        "setp.ne.u32 p, %4, 0;\n\t"
        "tcgen05.mma.cta_group::1.kind::f16 [%0], %1, %2, %3, {%5, %5, %5, %5}, p;\n\t}"
        :: "r"(d_tmem), "l"(a_desc), "l"(b_desc), "r"(idesc), "r"(enable), "r"(0u)
        : "memory");
}
__device__ __forceinline__ void mbar_wait(uint32_t mbar, uint32_t parity) {
    uint32_t done;
    asm volatile(
        "{\n\t.reg .pred p;\n\t"
        "mbarrier.try_wait.parity.acquire.cta.shared::cta.b64 p, [%1], %2;\n\t"
        "selp.b32 %0, 1, 0, p;\n\t}"
        : "=r"(done) : "r"(mbar), "r"(parity) : "memory");
    if (!done) {
        asm volatile(
            "{\n\t.reg .pred P1;\n\t"
            "WL_%=:\n\t"
            "mbarrier.try_wait.parity.acquire.cta.shared::cta.b64 P1, [%0], %1, 0x989680;\n\t"
            "@P1 bra.uni WD_%=;\n\t"
            "bra.uni WL_%=;\n\t"
            "WD_%=:\n\t}"
            :: "r"(mbar), "r"(parity) : "memory");
    }
}
__device__ __forceinline__ void mbar_arrive(uint32_t mbar) {
    asm volatile("mbarrier.arrive.release.cta.shared::cta.b64 _, [%0];"
                 :: "r"(mbar) : "memory");
}
__device__ __forceinline__ void cp_async_arrive_noinc(uint32_t mbar) {
    asm volatile("cp.async.mbarrier.arrive.noinc.shared::cta.b64 [%0];"
                 :: "r"(mbar) : "memory");
}

#define LDTM_X32(dr, addr)                                                     \
    asm volatile(                                                              \
        "tcgen05.ld.sync.aligned.32x32b.x32.b32 "                              \
        "{%0, %1, %2, %3, %4, %5, %6, %7, "                                    \
        " %8, %9, %10, %11, %12, %13, %14, %15, "                              \
        " %16, %17, %18, %19, %20, %21, %22, %23, "                            \
        " %24, %25, %26, %27, %28, %29, %30, %31}, [%32];"                     \
        : "=r"((dr)[0]),  "=r"((dr)[1]),  "=r"((dr)[2]),  "=r"((dr)[3]),       \
          "=r"((dr)[4]),  "=r"((dr)[5]),  "=r"((dr)[6]),  "=r"((dr)[7]),       \
          "=r"((dr)[8]),  "=r"((dr)[9]),  "=r"((dr)[10]), "=r"((dr)[11]),      \
          "=r"((dr)[12]), "=r"((dr)[13]), "=r"((dr)[14]), "=r"((dr)[15]),      \
          "=r"((dr)[16]), "=r"((dr)[17]), "=r"((dr)[18]), "=r"((dr)[19]),      \
          "=r"((dr)[20]), "=r"((dr)[21]), "=r"((dr)[22]), "=r"((dr)[23]),      \
          "=r"((dr)[24]), "=r"((dr)[25]), "=r"((dr)[26]), "=r"((dr)[27]),      \
          "=r"((dr)[28]), "=r"((dr)[29]), "=r"((dr)[30]), "=r"((dr)[31])       \
        : "r"(addr))

// Epilogue for one tile: this warp reads 64 columns [c0, c0+64) of its
// 32-lane subpartition. Hinge via max(d, 0.2): the constant -0.2*vm part is
// corrected once at the end (local -= 0.2*NT*sum_vm).
__device__ __forceinline__ void epi64(uint32_t tsrc, const float* vmv, float& local) {
    uint32_t dr[64];
    LDTM_X32(dr,      tsrc);
    LDTM_X32(dr + 32, tsrc + 32);
    asm volatile("tcgen05.wait::ld.sync.aligned;" ::: "memory");
    float a0 = 0.f, a1 = 0.f, a2 = 0.f, a3 = 0.f;
    #pragma unroll
    for (int k = 0; k < 64; k += 4) {
        a0 = fmaf(vmv[k + 0], fmaxf(__uint_as_float(dr[k + 0]), 0.2f), a0);
        a1 = fmaf(vmv[k + 1], fmaxf(__uint_as_float(dr[k + 1]), 0.2f), a1);
        a2 = fmaf(vmv[k + 2], fmaxf(__uint_as_float(dr[k + 2]), 0.2f), a2);
        a3 = fmaf(vmv[k + 3], fmaxf(__uint_as_float(dr[k + 3]), 0.2f), a3);
    }
    local += (a0 + a1) + (a2 + a3);
}
#endif

// ---------------------------------------------------------------------------
// Transpose + pad + bf16 convert: [n][c][m] f32 -> [n][m][c] bf16
// ---------------------------------------------------------------------------
__global__ void transpose_kernel(const float* __restrict__ d1,
                                 const float* __restrict__ d2) {
    __shared__ float t1[32][33];
    __shared__ float t2[32][33];
    int m0 = blockIdx.x * 32, c0 = blockIdx.y * 32, n = blockIdx.z;
    int tx = threadIdx.x, ty = threadIdx.y;   // 32 x 8

    #pragma unroll
    for (int i = 0; i < 4; i++) {
        int c = c0 + ty + i * 8, m = m0 + tx;
        float v1 = 0.f, v2 = 0.f;
        if (m < M) {
            size_t idx = ((size_t)n * C + c) * M + m;
            v1 = d1[idx]; v2 = d2[idx];
        }
        t1[ty + i * 8][tx] = v1;
        t2[ty + i * 8][tx] = v2;
    }
    __syncthreads();
    #pragma unroll
    for (int i = 0; i < 4; i++) {
        int m = m0 + ty + i * 8, c = c0 + tx;
        if (m < MP) {
            size_t o = ((size_t)n * MP + m) * C + c;
            d_D1t[o] = __float2bfloat16(t1[tx][ty + i * 8]);
            d_D2t[o] = __float2bfloat16(t2[tx][ty + i * 8]);
        }
    }
}

// ---------------------------------------------------------------------------
// Fallback prep (no-op on "a" targets)
// ---------------------------------------------------------------------------
__global__ void pad_kernel(const float* __restrict__ d1, const float* __restrict__ d2) {
#if !HAS_TC
    int idx = blockIdx.x * blockDim.x + threadIdx.x;
    if (idx >= NB * C * MP) return;
    int mp = idx % MP;
    int nc = idx / MP;
    float v1 = 0.f, v2 = 0.f;
    if (mp < M) {
        int s = nc * M + mp;
        v1 = d1[s];
        v2 = d2[s];
    }
    d_D1p[idx] = v1;
    d_D2p[idx] = v2;
#endif
}

// ---------------------------------------------------------------------------
// vm[n, i, j] = prod of 8x8 block of vis_mask1; padded entries are 0.
// ---------------------------------------------------------------------------
__global__ void vm_kernel(const float* __restrict__ vis) {
    int idx = blockIdx.x * blockDim.x + threadIdx.x;
    if (idx >= NB * MP) return;
    int mp = idx % MP;
    int n  = idx / MP;
    float p = 0.f;
    if (mp < M) {
        int i = mp / WR, j = mp % WR;
        p = 1.f;
        const float* base = vis + n * HH * WW + (i * GS) * WW + j * GS;
        #pragma unroll
        for (int a = 0; a < GS; a++)
            #pragma unroll
            for (int b = 0; b < GS; b++)
                p *= base[a * WW + b];
    }
    d_vm[idx] = p;
}

// ---------------------------------------------------------------------------
// Warp-specialized persistent-strip tcgen05 GEMM + hinge + reduce.
// Grid (29, 1, 4), 288 threads = 8 loader/epilogue warps + 1 MMA warp.
// B strip (full K) resident in smem; A tiles double-buffered via cp.async
// tracked by mbarriers (cp.async.mbarrier.arrive.noinc). MMA warp owns the
// tcgen05 dispatch queue stalls; epilogue warps never touch MMA issue.
// Dynamic smem: A0 @0 (64KB), A1 @65536 (64KB), B @131072 (64KB).
// mbarriers: loadrdy[2] (count 256), mmadone[2] (count 1, via commit),
//            epidone[2] (count 256).
// ---------------------------------------------------------------------------
__global__ __launch_bounds__(288, 1) void gemm_tc_kernel() {
#if HAS_TC
    extern __shared__ char dyn_sm[];
    __shared__ uint32_t s_tmem[1];
    __shared__ __align__(8) unsigned long long s_mbar[6]; // loadrdy0,1 mmadone0,1 epidone0,1
    __shared__ float s_red[8];

    const int n   = blockIdx.z;
    const int xs  = blockIdx.x;
    const int tid = threadIdx.x;
    const int wid = tid >> 5, lid = tid & 31;

    uint32_t raw  = smem_u32(dyn_sm);
    uint32_t base = (raw + 1023u) & ~1023u;

    if (wid == 8) {
        asm volatile("tcgen05.alloc.cta_group::1.sync.aligned.shared::cta.b32 [%0], %1;"
                     :: "r"(smem_u32(s_tmem)), "r"(256u) : "memory");
        asm volatile("tcgen05.relinquish_alloc_permit.cta_group::1.sync.aligned;");
    }
    if (tid == 0) {
        asm volatile("mbarrier.init.shared.b64 [%0], %1;" :: "r"(smem_u32(&s_mbar[0])), "r"(256u) : "memory");
        asm volatile("mbarrier.init.shared.b64 [%0], %1;" :: "r"(smem_u32(&s_mbar[1])), "r"(256u) : "memory");
        asm volatile("mbarrier.init.shared.b64 [%0], %1;" :: "r"(smem_u32(&s_mbar[2])), "r"(1u)   : "memory");
        asm volatile("mbarrier.init.shared.b64 [%0], %1;" :: "r"(smem_u32(&s_mbar[3])), "r"(1u)   : "memory");
        asm volatile("mbarrier.init.shared.b64 [%0], %1;" :: "r"(smem_u32(&s_mbar[4])), "r"(256u) : "memory");
        asm volatile("mbarrier.init.shared.b64 [%0], %1;" :: "r"(smem_u32(&s_mbar[5])), "r"(256u) : "memory");
    }
    __syncthreads();
    const uint32_t tmem = s_tmem[0];
    const uint32_t mb_load[2] = { smem_u32(&s_mbar[0]), smem_u32(&s_mbar[1]) };
    const uint32_t mb_mma[2]  = { smem_u32(&s_mbar[2]), smem_u32(&s_mbar[3]) };
    const uint32_t mb_epi[2]  = { smem_u32(&s_mbar[4]), smem_u32(&s_mbar[5]) };

    const __nv_bfloat16* Abase = d_D1t + (size_t)n * MP * C;
    const __nv_bfloat16* Bg    = d_D2t + ((size_t)n * MP + xs * BN) * C;

    if (wid < 8) {
        // ---------------- loader / epilogue warps (256 threads) ----------------
        const int c0 = (wid >= 4) ? 64 : 0;
        float vmv[64];
        float sum_vm = 0.f;
        {
            const float* vmb = d_vm + n * MP + xs * BN + c0;
            #pragma unroll
            for (int k = 0; k < 64; k++) { vmv[k] = vmb[k]; sum_vm += vmb[k]; }
        }

        // load mapping: 4096 16B vectors / 64KB buffer; 16 per thread.
        // vi = i*256+tid; row = vi>>5, vec = vi&31;
        // off = (vec>>3)*16384 + SWZ128(row*128 + (vec&7)*16)

        // prologue: B + A0 -> arrive loadrdy[0]; A1 -> arrive loadrdy[1]
        #pragma unroll
        for (int i = 0; i < 16; i++) {
            int vi = i * 256 + tid;
            int row = vi >> 5, vec = vi & 31;
            uint32_t off = (uint32_t)((vec >> 3) * 16384) + SWZ128((uint32_t)(row * 128 + (vec & 7) * 16));
            cp_async16(base + 131072 + off, Bg + (size_t)row * C + vec * 8);
            cp_async16(base + off,          Abase + (size_t)row * C + vec * 8);
        }
        cp_async_arrive_noinc(mb_load[0]);
        #pragma unroll
        for (int i = 0; i < 16; i++) {
            int vi = i * 256 + tid;
            int row = vi >> 5, vec = vi & 31;
            uint32_t off = (uint32_t)((vec >> 3) * 16384) + SWZ128((uint32_t)(row * 128 + (vec & 7) * 16));
            cp_async16(base + 65536 + off, Abase + (size_t)BM * C + (size_t)row * C + vec * 8);
        }
        cp_async_arrive_noinc(mb_load[1]);

        uint32_t phm[2] = {0u, 0u};
        float local = 0.f;

        #pragma unroll 1
        for (int t = 1; t < NT; t++) {
            const int pb = (t - 1) & 1;
            // MMA t-1 done -> tmem[pb] ready, buf[pb] free
            mbar_wait(mb_mma[pb], phm[pb]);
            phm[pb] ^= 1u;

            // prefetch A[t+1] into buf[pb]; signal loadrdy[pb] on completion
            if (t + 1 < NT) {
                const __nv_bfloat16* An = Abase + (size_t)(t + 1) * BM * C;
                #pragma unroll
                for (int i = 0; i < 16; i++) {
                    int vi = i * 256 + tid;
                    int row = vi >> 5, vec = vi & 31;
                    uint32_t off = (uint32_t)((vec >> 3) * 16384)
                                 + SWZ128((uint32_t)(row * 128 + (vec & 7) * 16));
                    cp_async16(base + pb * 65536 + off, An + (size_t)row * C + vec * 8);
                }
                cp_async_arrive_noinc(mb_load[pb]);
            }

            // epilogue tile t-1 (overlaps MMA t, issued independently by warp 8)
            asm volatile("tcgen05.fence::after_thread_sync;" ::: "memory");
            epi64(tmem + pb * 128 + c0, vmv, local);
            asm volatile("tcgen05.fence::before_thread_sync;" ::: "memory");
            mbar_arrive(mb_epi[pb]);   // tmem[pb] consumed
        }

        // tail epilogue: tile NT-1
        {
            const int pb = (NT - 1) & 1;
            mbar_wait(mb_mma[pb], phm[pb]);
            asm volatile("tcgen05.fence::after_thread_sync;" ::: "memory");
            epi64(tmem + pb * 128 + c0, vmv, local);
        }

        // fold out the constant -0.2*vm part of the hinge
        local -= 0.2f * (float)NT * sum_vm;

        #pragma unroll
        for (int o = 16; o > 0; o >>= 1)
            local += __shfl_down_sync(0xffffffffu, local, o);
        if (lid == 0) s_red[wid] = local;
    } else {
        // ---------------- MMA warp ----------------
        uint32_t phl[2] = {0u, 0u};
        uint32_t phe[2] = {0u, 0u};
        const bool leader = elect_one() != 0;

        #pragma unroll 1
        for (int t = 0; t < NT; t++) {
            const int b = t & 1;
            mbar_wait(mb_load[b], phl[b]);      // A[t] (and B for t==0) in smem
            phl[b] ^= 1u;
            if (t >= 2) {                       // tmem[b] free of tile t-2 reads
                mbar_wait(mb_epi[b], phe[b]);
                phe[b] ^= 1u;
            }
            asm volatile("fence.proxy.async.shared::cta;" ::: "memory");
            if (leader) {
                const uint32_t dt = tmem + b * 128;
                #pragma unroll
                for (int c = 0; c < 4; c++) {
                    uint64_t ad = make_desc(base + b * 65536 + c * 16384);
                    uint64_t bd = make_desc(base + 131072 + c * 16384);
                    #pragma unroll
                    for (int ks = 0; ks < 4; ks++)
                        mma_f16_ss_cg1(dt, ad + ks * 2, bd + ks * 2, MMA_IDESC,
                                       (uint32_t)(c * 4 + ks));
                }
                asm volatile(
                    "tcgen05.commit.cta_group::1.mbarrier::arrive::one.shared::cluster.b64 [%0];"
                    :: "r"(mb_mma[b]) : "memory");
            }
        }
    }

    __syncthreads();
    if (tid == 0) {
        float t = 0.f;
        #pragma unroll
        for (int w = 0; w < 8; w++) t += s_red[w];
        d_partA[n * GB + xs] = t;
    }
    if (wid == 8) {
        asm volatile("tcgen05.dealloc.cta_group::1.sync.aligned.b32 %0, %1;"
                     :: "r"(tmem), "r"(256u));
    }
#endif
}

// ---------------------------------------------------------------------------
// Fallback SIMT fp32 GEMM (active only WITHOUT tcgen05). Round-1 tiling.
// ---------------------------------------------------------------------------
__global__ __launch_bounds__(256, 2) void gemm_simt_kernel() {
#if !HAS_TC
    int n = blockIdx.z;
    const float* Ab = d_D1p + n * C * MP + blockIdx.y * BM;
    const float* Bb = d_D2p + n * C * MP + blockIdx.x * BN;

    __shared__ float As[2][BK][BM];
    __shared__ float Bs[2][BK][BN];

    int tid  = threadIdx.x;
    int tx   = tid & 15;
    int ty   = tid >> 4;
    int lrow = tid >> 5;
    int lcol = (tid & 31) << 2;

    float acc[8][8];
    #pragma unroll
    for (int i = 0; i < 8; i++)
        #pragma unroll
        for (int j = 0; j < 8; j++) acc[i][j] = 0.f;

    *(float4*)&As[0][lrow][lcol] = *(const float4*)&Ab[lrow * MP + lcol];
    *(float4*)&Bs[0][lrow][lcol] = *(const float4*)&Bb[lrow * MP + lcol];
    __syncthreads();

    #pragma unroll 1
    for (int k0 = 0; k0 < C; k0 += BK) {
        int buf = (k0 >> 3) & 1;
        if (k0 + BK < C) {
            *(float4*)&As[buf ^ 1][lrow][lcol] =
                *(const float4*)&Ab[(k0 + BK + lrow) * MP + lcol];
            *(float4*)&Bs[buf ^ 1][lrow][lcol] =
                *(const float4*)&Bb[(k0 + BK + lrow) * MP + lcol];
        }
        #pragma unroll
        for (int kk = 0; kk < BK; kk++) {
            float a[8], b[8];
            *(float4*)&a[0] = *(const float4*)&As[buf][kk][ty * 8];
            *(float4*)&a[4] = *(const float4*)&As[buf][kk][ty * 8 + 4];
            *(float4*)&b[0] = *(const float4*)&Bs[buf][kk][tx * 8];
            *(float4*)&b[4] = *(const float4*)&Bs[buf][kk][tx * 8 + 4];
            #pragma unroll
            for (int i = 0; i < 8; i++)
                #pragma unroll
                for (int j = 0; j < 8; j++)
                    acc[i][j] = fmaf(a[i], b[j], acc[i][j]);
        }
        __syncthreads();
    }

    float vmv[8];
    #pragma unroll
    for (int j = 0; j < 8; j++)
        vmv[j] = d_vm[n * MP + blockIdx.x * BN + tx * 8 + j];

    float local = 0.f;
    #pragma unroll
    for (int i = 0; i < 8; i++)
        #pragma unroll
        for (int j = 0; j < 8; j++)
            local += vmv[j] * fmaxf(acc[i][j] - 0.2f, 0.f);

    #pragma unroll
    for (int o = 16; o > 0; o >>= 1)
        local += __shfl_down_sync(0xffffffffu, local, o);

    __shared__ float wsum[8];
    if ((tid & 31) == 0) wsum[tid >> 5] = local;
    __syncthreads();
    if (tid == 0) {
        float t = 0.f;
        #pragma unroll
        for (int w = 0; w < 8; w++) t += wsum[w];
        d_partA[(blockIdx.z * GB + blockIdx.y) * GB + blockIdx.x] = t;
    }
#endif
}

// ---------------------------------------------------------------------------
// Positive-pair correction (coalesced bf16 dots on transposed arrays).
// ---------------------------------------------------------------------------
__device__ __forceinline__ float dot8(uint4 a, uint4 b) {
    const __nv_bfloat162* pa = (const __nv_bfloat162*)&a;
    const __nv_bfloat162* pb = (const __nv_bfloat162*)&b;
    float s = 0.f;
    #pragma unroll
    for (int k = 0; k < 4; k++) {
        float2 fa = __bfloat1622float2(pa[k]);
        float2 fb = __bfloat1622float2(pb[k]);
        s += fa.x * fb.x + fa.y * fb.y;
    }
    return s;
}

__global__ void pos_kernel(const float* __restrict__ homo) {
    int warp = threadIdx.x >> 5;
    int lane = threadIdx.x & 31;
    int item = blockIdx.x * 8 + warp;   // 0 .. 14399
    float contrib = 0.f;

    if (item < NB * M) {
        int n  = item / M;
        int ij = item % M;
        int i  = ij / WR, j = ij % WR;
        float x = j * 8 + 4.f, y = i * 8 + 4.f;
        const float* Hm = homo + n * 9;
        float wxh = Hm[0] * x + Hm[1] * y + Hm[2];
        float wyh = Hm[3] * x + Hm[4] * y + Hm[5];
        float wzh = Hm[6] * x + Hm[7] * y + Hm[8];
        float wx = wxh / wzh, wy = wyh / wzh;
        float vmv = d_vm[n * MP + ij];

        const uint4 bvec = ((const uint4*)(d_D2t + ((size_t)n * MP + ij) * C))[lane];

        int hs = (int)floorf((wy - 11.5f) * 0.125f);
        int ws = (int)floorf((wx - 11.5f) * 0.125f);
        for (int hh = hs; hh < hs + 4; hh++) {
            if (hh < 0 || hh >= HR) continue;
            float dy = hh * 8 + 4.f - wy;
            for (int wc = ws; wc < ws + 4; wc++) {
                if (wc < 0 || wc >= WR) continue;
                float dx = wc * 8 + 4.f - wx;
                if (dx * dx + dy * dy <= 56.25f) {   // dist <= 7.5
                    const uint4 avec =
                        ((const uint4*)(d_D1t + ((size_t)n * MP + hh * WR + wc) * C))[lane];
                    float dt = dot8(avec, bvec);
                    #pragma unroll
                    for (int o = 16; o > 0; o >>= 1)
                        dt += __shfl_down_sync(0xffffffffu, dt, o);
                    dt = __shfl_sync(0xffffffffu, dt, 0);
                    if (lane == 0)
                        contrib += vmv * (fmaxf(1.f - dt, 0.f) - fmaxf(dt - 0.2f, 0.f));
                }
            }
        }
    }

    __shared__ float wsh[8];
    if (lane == 0) wsh[warp] = contrib;
    __syncthreads();
    if (threadIdx.x == 0) {
        float t = 0.f;
        #pragma unroll
        for (int w = 0; w < 8; w++) t += wsh[w];
        d_partB[blockIdx.x] = t;
    }
}

// ---------------------------------------------------------------------------
// Final deterministic reduction. partA bound matches the active GEMM path.
// ---------------------------------------------------------------------------
__global__ void final_kernel(float* __restrict__ out) {
    __shared__ float sh[256];
    int tid = threadIdx.x;

#if HAS_TC
    const int NPA = NB * GB;        // 116 strip partials
#else
    const int NPA = GB * GB * NB;   // 3364 tile partials
#endif

    float s = 0.f;
    for (int k = tid; k < NPA; k += 256) s += d_partA[k];
    for (int k = tid; k < NPOSB; k += 256) s += d_partB[k];
    float v = 0.f;
    for (int k = tid; k < NB * MP; k += 256) v += d_vm[k];  // pads are 0

    sh[tid] = s;
    __syncthreads();
    for (int o = 128; o > 0; o >>= 1) {
        if (tid < o) sh[tid] += sh[tid + o];
        __syncthreads();
    }
    float total = sh[0];
    __syncthreads();

    sh[tid] = v;
    __syncthreads();
    for (int o = 128; o > 0; o >>= 1) {
        if (tid < o) sh[tid] += sh[tid + o];
        __syncthreads();
    }
    if (tid == 0)
        out[0] = total / (3600.f * sh[0]);   // LOSS_LAMBDA = 1
}

// ---------------------------------------------------------------------------
extern "C" void kernel_launch(void* const* d_in, const int* in_sizes, int n_in,
                              void* d_out, int out_size) {
    const float* desc1 = nullptr;
    const float* desc2 = nullptr;
    const float* homo  = nullptr;
    const float* vis   = nullptr;
    for (int k = 0; k < n_in; k++) {
        if (in_sizes[k] == NB * C * M) {
            if (!desc1) desc1 = (const float*)d_in[k];
            else if (!desc2) desc2 = (const float*)d_in[k];
        } else if (in_sizes[k] == NB * 9) {
            homo = (const float*)d_in[k];
        } else if (in_sizes[k] == NB * HH * WW) {
            vis = (const float*)d_in[k];
        }
    }

    // Idempotent, capture-safe.
    cudaFuncSetAttribute(gemm_tc_kernel,
                         cudaFuncAttributeMaxDynamicSharedMemorySize, 197632);

    transpose_kernel<<<dim3(116, 8, NB), dim3(32, 8)>>>(desc1, desc2);
    vm_kernel<<<(NB * MP + 255) / 256, 256>>>(vis);
    pad_kernel<<<(NB * C * MP + 255) / 256, 256>>>(desc1, desc2);   // no-op on "a"
    gemm_tc_kernel<<<dim3(GB, 1, NB), 288, 197632>>>();             // active on "a"
    gemm_simt_kernel<<<dim3(GB, GB, NB), 256>>>();                  // active otherwise
    pos_kernel<<<NPOSB, 256>>>(homo);
    final_kernel<<<1, 256>>>((float*)d_out);
}

// round 8
// speedup vs baseline: 10.6255x; 1.0941x over previous
#include <cuda_runtime.h>
#include <cuda_bf16.h>
#include <cstdint>

// ---------------------------------------------------------------------------
// Arch feature gate: tcgen05/TMEM are "a"-target-only. Non-"a" passes compile
// the SIMT fallback instead; exactly one GEMM kernel is active per pass.
// ---------------------------------------------------------------------------
#if defined(__CUDA_ARCH__) && (defined(__CUDA_ARCH_FEAT_SM103_ALL) || defined(__CUDA_ARCH_FEAT_SM100_ALL))
#define HAS_TC 1
#else
#define HAS_TC 0
#endif

// Problem constants
#define NB 4
#define C  256
#define HR 60
#define WR 60
#define M  3600          // HR*WR
#define MP 3712          // padded to 29*128
#define GS 8
#define HH 480
#define WW 480

#define BM 128
#define BN 128
#define BK 8
#define GB 29            // tiles per GEMM dim
#define NT 29            // A tiles per strip (persistent loop)
#define NH (2 * NT)      // K=128 half-tiles
#define NPOSB 1800

// idesc kind::f16: dtype=F32(1<<4), atype=BF16(1<<7), btype=BF16(1<<10),
// N/8 << 17, M/16 << 24  ->  M=128, N=128
#define MMA_IDESC 0x8200490u

// smem layout (dynamic, 1024-aligned): A slots 0..4 @ s*32768 (32KB each),
// B @ 131072 (64KB). Total 192KB.
#define A_SLOT(s)  ((uint32_t)(s) * 32768u)
#define B_OFF      131072u

// __device__ scratch (no allocation allowed)
__device__ __align__(16) __nv_bfloat16 d_D1t[(size_t)NB * MP * C];  // [n][m][c] bf16
__device__ __align__(16) __nv_bfloat16 d_D2t[(size_t)NB * MP * C];
__device__ float d_D1p[NB * C * MP];                                // fp32 fallback
__device__ float d_D2p[NB * C * MP];
__device__ float d_vm[NB * MP];
__device__ float d_partA[GB * GB * NB];
__device__ float d_partB[NPOSB];

// ---------------------------------------------------------------------------
// Helpers
// ---------------------------------------------------------------------------
__device__ __forceinline__ uint32_t smem_u32(const void* p) {
    uint32_t a;
    asm("{ .reg .u64 t; cvta.to.shared.u64 t, %1; cvt.u32.u64 %0, t; }" : "=r"(a) : "l"(p));
    return a;
}
#define SWZ128(off) ((off) ^ (((off) >> 3) & 0x70))

__device__ __forceinline__ void cp_async16(uint32_t dst, const void* src) {
    asm volatile("cp.async.cg.shared.global [%0], [%1], 16;"
                 :: "r"(dst), "l"(src) : "memory");
}

#if HAS_TC
__device__ __forceinline__ uint32_t elect_one() {
    uint32_t p;
    asm volatile("{ .reg .pred p; elect.sync _|p, 0xFFFFFFFF; selp.b32 %0, 1, 0, p; }" : "=r"(p));
    return p;
}
static __device__ __forceinline__ uint64_t make_desc(uint32_t addr) {
    // SW128, version=1(Blackwell), SBO=64, LBO=1
    const uint64_t base = (uint64_t(2) << 61) | (uint64_t(1) << 46)
                        | (uint64_t(64) << 32) | (uint64_t(1) << 16);
    return base | ((uint64_t)(addr >> 4) & 0x3FFF);
}
__device__ __forceinline__ void mma_f16_ss_cg1(uint32_t d_tmem, uint64_t a_desc,
                                               uint64_t b_desc, uint32_t idesc,
                                               uint32_t enable) {
    asm volatile(
        "{\n\t.reg .pred p;\n\t"
        "setp.ne.u32 p, %4, 0;\n\t"
        "tcgen05.mma.cta_group::1.kind::f16 [%0], %1, %2, %3, {%5, %5, %5, %5}, p;\n\t}"
        :: "r"(d_tmem), "l"(a_desc), "l"(b_desc), "r"(idesc), "r"(enable), "r"(0u)
        : "memory");
}
__device__ __forceinline__ void mbar_wait(uint32_t mbar, uint32_t parity) {
    uint32_t done;
    asm volatile(
        "{\n\t.reg .pred p;\n\t"
        "mbarrier.try_wait.parity.acquire.cta.shared::cta.b64 p, [%1], %2;\n\t"
        "selp.b32 %0, 1, 0, p;\n\t}"
        : "=r"(done) : "r"(mbar), "r"(parity) : "memory");
    if (!done) {
        asm volatile(
            "{\n\t.reg .pred P1;\n\t"
            "WL_%=:\n\t"
            "mbarrier.try_wait.parity.acquire.cta.shared::cta.b64 P1, [%0], %1, 0x989680;\n\t"
            "@P1 bra.uni WD_%=;\n\t"
            "bra.uni WL_%=;\n\t"
            "WD_%=:\n\t}"
            :: "r"(mbar), "r"(parity) : "memory");
    }
}
__device__ __forceinline__ void mbar_arrive(uint32_t mbar) {
    asm volatile("mbarrier.arrive.release.cta.shared::cta.b64 _, [%0];"
                 :: "r"(mbar) : "memory");
}
__device__ __forceinline__ void cp_async_arrive_noinc(uint32_t mbar) {
    asm volatile("cp.async.mbarrier.arrive.noinc.shared::cta.b64 [%0];"
                 :: "r"(mbar) : "memory");
}

#define LDTM_X32(dr, addr)                                                     \
    asm volatile(                                                              \
        "tcgen05.ld.sync.aligned.32x32b.x32.b32 "                              \
        "{%0, %1, %2, %3, %4, %5, %6, %7, "                                    \
        " %8, %9, %10, %11, %12, %13, %14, %15, "                              \
        " %16, %17, %18, %19, %20, %21, %22, %23, "                            \
        " %24, %25, %26, %27, %28, %29, %30, %31}, [%32];"                     \
        : "=r"((dr)[0]),  "=r"((dr)[1]),  "=r"((dr)[2]),  "=r"((dr)[3]),       \
          "=r"((dr)[4]),  "=r"((dr)[5]),  "=r"((dr)[6]),  "=r"((dr)[7]),       \
          "=r"((dr)[8]),  "=r"((dr)[9]),  "=r"((dr)[10]), "=r"((dr)[11]),      \
          "=r"((dr)[12]), "=r"((dr)[13]), "=r"((dr)[14]), "=r"((dr)[15]),      \
          "=r"((dr)[16]), "=r"((dr)[17]), "=r"((dr)[18]), "=r"((dr)[19]),      \
          "=r"((dr)[20]), "=r"((dr)[21]), "=r"((dr)[22]), "=r"((dr)[23]),      \
          "=r"((dr)[24]), "=r"((dr)[25]), "=r"((dr)[26]), "=r"((dr)[27]),      \
          "=r"((dr)[28]), "=r"((dr)[29]), "=r"((dr)[30]), "=r"((dr)[31])       \
        : "r"(addr))

// Epilogue for one tile: this warp reads 64 columns [c0, c0+64) of its
// 32-lane subpartition. Hinge via max(d, 0.2); the constant -0.2*vm part is
// folded out once at the end (local -= 0.2*NT*sum_vm).
__device__ __forceinline__ void epi64(uint32_t tsrc, const float* vmv, float& local) {
    uint32_t dr[64];
    LDTM_X32(dr,      tsrc);
    LDTM_X32(dr + 32, tsrc + 32);
    asm volatile("tcgen05.wait::ld.sync.aligned;" ::: "memory");
    float a0 = 0.f, a1 = 0.f, a2 = 0.f, a3 = 0.f;
    #pragma unroll
    for (int k = 0; k < 64; k += 4) {
        a0 = fmaf(vmv[k + 0], fmaxf(__uint_as_float(dr[k + 0]), 0.2f), a0);
        a1 = fmaf(vmv[k + 1], fmaxf(__uint_as_float(dr[k + 1]), 0.2f), a1);
        a2 = fmaf(vmv[k + 2], fmaxf(__uint_as_float(dr[k + 2]), 0.2f), a2);
        a3 = fmaf(vmv[k + 3], fmaxf(__uint_as_float(dr[k + 3]), 0.2f), a3);
    }
    local += (a0 + a1) + (a2 + a3);
}
#endif

// ---------------------------------------------------------------------------
// Transpose + pad + bf16 convert: [n][c][m] f32 -> [n][m][c] bf16.
// On non-"a" targets it ALSO writes the zero-padded fp32 copies for the SIMT
// fallback (fused former pad_kernel).
// ---------------------------------------------------------------------------
__global__ void transpose_kernel(const float* __restrict__ d1,
                                 const float* __restrict__ d2) {
    __shared__ float t1[32][33];
    __shared__ float t2[32][33];
    int m0 = blockIdx.x * 32, c0 = blockIdx.y * 32, n = blockIdx.z;
    int tx = threadIdx.x, ty = threadIdx.y;   // 32 x 8

    #pragma unroll
    for (int i = 0; i < 4; i++) {
        int c = c0 + ty + i * 8, m = m0 + tx;
        float v1 = 0.f, v2 = 0.f;
        if (m < M) {
            size_t idx = ((size_t)n * C + c) * M + m;
            v1 = d1[idx]; v2 = d2[idx];
        }
        t1[ty + i * 8][tx] = v1;
        t2[ty + i * 8][tx] = v2;
#if !HAS_TC
        // fused pad for the SIMT fallback ([n][c][m] padded, coalesced in m)
        size_t o = ((size_t)n * C + c) * MP + m;
        d_D1p[o] = v1;
        d_D2p[o] = v2;
#endif
    }
    __syncthreads();
    #pragma unroll
    for (int i = 0; i < 4; i++) {
        int m = m0 + ty + i * 8, c = c0 + tx;
        if (m < MP) {
            size_t o = ((size_t)n * MP + m) * C + c;
            d_D1t[o] = __float2bfloat16(t1[tx][ty + i * 8]);
            d_D2t[o] = __float2bfloat16(t2[tx][ty + i * 8]);
        }
    }
}

// ---------------------------------------------------------------------------
// vm[n, i, j] = prod of 8x8 block of vis_mask1; padded entries are 0.
// ---------------------------------------------------------------------------
__global__ void vm_kernel(const float* __restrict__ vis) {
    int idx = blockIdx.x * blockDim.x + threadIdx.x;
    if (idx >= NB * MP) return;
    int mp = idx % MP;
    int n  = idx / MP;
    float p = 0.f;
    if (mp < M) {
        int i = mp / WR, j = mp % WR;
        p = 1.f;
        const float* base = vis + n * HH * WW + (i * GS) * WW + j * GS;
        #pragma unroll
        for (int a = 0; a < GS; a++)
            #pragma unroll
            for (int b = 0; b < GS; b++)
                p *= base[a * WW + b];
    }
    d_vm[idx] = p;
}

// ---------------------------------------------------------------------------
// Warp-specialized persistent-strip tcgen05 GEMM + hinge + reduce.
// Grid (29, 1, 4), 288 threads = 8 loader/epilogue warps + 1 MMA warp.
// B strip (full K) resident; A streamed as K=128 HALF-tiles through a 4-slot
// ring (32KB each) -> loads get a ~2-tile landing window and leave the
// critical path. Commit-per-half signals both slot reuse (loader) and tile
// completion (epilogue waits the odd half's commit).
// mbarriers: loadrdy[4] (count 256, cp.async-tracked), half[4] (count 1,
// commit), epi[2] (count 256, tmem buffer reuse).
// ---------------------------------------------------------------------------
__global__ __launch_bounds__(288, 1) void gemm_tc_kernel() {
#if HAS_TC
    extern __shared__ char dyn_sm[];
    __shared__ uint32_t s_tmem[1];
    __shared__ __align__(8) unsigned long long s_mbar[10]; // loadrdy[4] half[4] epi[2]
    __shared__ float s_red[8];

    const int n   = blockIdx.z;
    const int xs  = blockIdx.x;
    const int tid = threadIdx.x;
    const int wid = tid >> 5, lid = tid & 31;

    uint32_t raw  = smem_u32(dyn_sm);
    uint32_t base = (raw + 1023u) & ~1023u;

    if (wid == 8) {
        asm volatile("tcgen05.alloc.cta_group::1.sync.aligned.shared::cta.b32 [%0], %1;"
                     :: "r"(smem_u32(s_tmem)), "r"(256u) : "memory");
        asm volatile("tcgen05.relinquish_alloc_permit.cta_group::1.sync.aligned;");
    }
    if (tid == 0) {
        #pragma unroll
        for (int k = 0; k < 4; k++)
            asm volatile("mbarrier.init.shared.b64 [%0], %1;"
                         :: "r"(smem_u32(&s_mbar[k])), "r"(256u) : "memory");
        #pragma unroll
        for (int k = 4; k < 8; k++)
            asm volatile("mbarrier.init.shared.b64 [%0], %1;"
                         :: "r"(smem_u32(&s_mbar[k])), "r"(1u) : "memory");
        #pragma unroll
        for (int k = 8; k < 10; k++)
            asm volatile("mbarrier.init.shared.b64 [%0], %1;"
                         :: "r"(smem_u32(&s_mbar[k])), "r"(256u) : "memory");
    }
    __syncthreads();
    const uint32_t tmem = s_tmem[0];
    uint32_t mb_load[4], mb_half[4], mb_epi[2];
    #pragma unroll
    for (int k = 0; k < 4; k++) { mb_load[k] = smem_u32(&s_mbar[k]); mb_half[k] = smem_u32(&s_mbar[4 + k]); }
    mb_epi[0] = smem_u32(&s_mbar[8]); mb_epi[1] = smem_u32(&s_mbar[9]);

    const __nv_bfloat16* Abase = d_D1t + (size_t)n * MP * C;
    const __nv_bfloat16* Bg    = d_D2t + ((size_t)n * MP + xs * BN) * C;

    if (wid < 8) {
        // ---------------- loader / epilogue warps (256 threads) ----------------
        const int c0 = (wid >= 4) ? 64 : 0;
        float vmv[64];
        float sum_vm = 0.f;
        {
            const float* vmb = d_vm + n * MP + xs * BN + c0;
            #pragma unroll
            for (int k = 0; k < 64; k++) { vmv[k] = vmb[k]; sum_vm += vmb[k]; }
        }

        // half-load: 2048 16B vectors (32KB); 8 per thread.
        // vi = i*256+tid; row = vi>>4 (0..127), vec = vi&15 (16B within 256B)
        // slot off = (vec>>3)*16384 + SWZ128(row*128 + (vec&7)*16)
        auto load_half = [&](int h) {
            const int t = h >> 1, ko = (h & 1) * 128, s = h & 3;
            const __nv_bfloat16* src = Abase + (size_t)t * BM * C + ko;
            #pragma unroll
            for (int i = 0; i < 8; i++) {
                int vi = i * 256 + tid;
                int row = vi >> 4, vec = vi & 15;
                uint32_t off = A_SLOT(s) + (uint32_t)((vec >> 3) * 16384)
                             + SWZ128((uint32_t)(row * 128 + (vec & 7) * 16));
                cp_async16(base + off, src + (size_t)row * C + vec * 8);
            }
            cp_async_arrive_noinc(mb_load[s]);
        };

        // prologue: B (64KB) then halves 0..3 (tiles 0,1)
        #pragma unroll
        for (int i = 0; i < 16; i++) {
            int vi = i * 256 + tid;
            int row = vi >> 5, vec = vi & 31;
            uint32_t off = B_OFF + (uint32_t)((vec >> 3) * 16384)
                         + SWZ128((uint32_t)(row * 128 + (vec & 7) * 16));
            cp_async16(base + off, Bg + (size_t)row * C + vec * 8);
        }
        load_half(0);
        load_half(1);
        load_half(2);
        load_half(3);

        int phh[4] = {0, 0, 0, 0};   // per-slot wait counters for mb_half
        float local = 0.f;

        #pragma unroll 1
        for (int t = 1; t < NT; t++) {
            const int h = 2 * t - 1;        // odd half of tile t-1
            const int s = h & 3;
            mbar_wait(mb_half[s], (uint32_t)(phh[s] & 1));
            phh[s]++;
            // tile t-1 fully done: tmem[(t-1)&1] final; slots of halves
            // 2t-2, 2t-1 free -> prefetch tile t+1's halves into them.
            if (t + 1 < NT) {
                load_half(2 * t + 2);
                load_half(2 * t + 3);
            }
            asm volatile("tcgen05.fence::after_thread_sync;" ::: "memory");
            epi64(tmem + ((t - 1) & 1) * 128 + c0, vmv, local);
            mbar_arrive(mb_epi[(t - 1) & 1]);   // tmem[(t-1)&1] consumed
        }

        // tail epilogue: tile NT-1 (odd half NH-1)
        {
            const int s = (NH - 1) & 3;
            mbar_wait(mb_half[s], (uint32_t)(phh[s] & 1));
            asm volatile("tcgen05.fence::after_thread_sync;" ::: "memory");
            epi64(tmem + ((NT - 1) & 1) * 128 + c0, vmv, local);
        }

        // fold out the constant -0.2*vm part of the hinge
        local -= 0.2f * (float)NT * sum_vm;

        #pragma unroll
        for (int o = 16; o > 0; o >>= 1)
            local += __shfl_down_sync(0xffffffffu, local, o);
        if (lid == 0) s_red[wid] = local;
    } else {
        // ---------------- MMA warp ----------------
        int pl[4] = {0, 0, 0, 0};
        int pe[2] = {0, 0};
        const bool leader = elect_one() != 0;

        #pragma unroll 1
        for (int t = 0; t < NT; t++) {
            if (t >= 2) {                       // tmem[t&1] free of tile t-2 reads
                mbar_wait(mb_epi[t & 1], (uint32_t)(pe[t & 1] & 1));
                pe[t & 1]++;
            }
            const uint32_t dt = tmem + (t & 1) * 128;
            #pragma unroll
            for (int half = 0; half < 2; half++) {
                const int h = 2 * t + half, s = h & 3;
                mbar_wait(mb_load[s], (uint32_t)(pl[s] & 1));
                pl[s]++;
                asm volatile("fence.proxy.async.shared::cta;" ::: "memory");
                if (leader) {
                    #pragma unroll
                    for (int c = 0; c < 2; c++) {
                        uint64_t ad = make_desc(base + A_SLOT(s) + c * 16384);
                        uint64_t bd = make_desc(base + B_OFF + ((h & 1) * 2 + c) * 16384);
                        #pragma unroll
                        for (int ks = 0; ks < 4; ks++)
                            mma_f16_ss_cg1(dt, ad + ks * 2, bd + ks * 2, MMA_IDESC,
                                           (uint32_t)(half | c | ks));
                    }
                    asm volatile(
                        "tcgen05.commit.cta_group::1.mbarrier::arrive::one.shared::cluster.b64 [%0];"
                        :: "r"(mb_half[s]) : "memory");
                }
            }
        }
    }

    __syncthreads();
    if (tid == 0) {
        float t = 0.f;
        #pragma unroll
        for (int w = 0; w < 8; w++) t += s_red[w];
        d_partA[n * GB + xs] = t;
    }
    if (wid == 8) {
        asm volatile("tcgen05.dealloc.cta_group::1.sync.aligned.b32 %0, %1;"
                     :: "r"(tmem), "r"(256u));
    }
#endif
}

// ---------------------------------------------------------------------------
// Fallback SIMT fp32 GEMM (active only WITHOUT tcgen05). Round-1 tiling.
// ---------------------------------------------------------------------------
__global__ __launch_bounds__(256, 2) void gemm_simt_kernel() {
#if !HAS_TC
    int n = blockIdx.z;
    const float* Ab = d_D1p + n * C * MP + blockIdx.y * BM;
    const float* Bb = d_D2p + n * C * MP + blockIdx.x * BN;

    __shared__ float As[2][BK][BM];
    __shared__ float Bs[2][BK][BN];

    int tid  = threadIdx.x;
    int tx   = tid & 15;
    int ty   = tid >> 4;
    int lrow = tid >> 5;
    int lcol = (tid & 31) << 2;

    float acc[8][8];
    #pragma unroll
    for (int i = 0; i < 8; i++)
        #pragma unroll
        for (int j = 0; j < 8; j++) acc[i][j] = 0.f;

    *(float4*)&As[0][lrow][lcol] = *(const float4*)&Ab[lrow * MP + lcol];
    *(float4*)&Bs[0][lrow][lcol] = *(const float4*)&Bb[lrow * MP + lcol];
    __syncthreads();

    #pragma unroll 1
    for (int k0 = 0; k0 < C; k0 += BK) {
        int buf = (k0 >> 3) & 1;
        if (k0 + BK < C) {
            *(float4*)&As[buf ^ 1][lrow][lcol] =
                *(const float4*)&Ab[(k0 + BK + lrow) * MP + lcol];
            *(float4*)&Bs[buf ^ 1][lrow][lcol] =
                *(const float4*)&Bb[(k0 + BK + lrow) * MP + lcol];
        }
        #pragma unroll
        for (int kk = 0; kk < BK; kk++) {
            float a[8], b[8];
            *(float4*)&a[0] = *(const float4*)&As[buf][kk][ty * 8];
            *(float4*)&a[4] = *(const float4*)&As[buf][kk][ty * 8 + 4];
            *(float4*)&b[0] = *(const float4*)&Bs[buf][kk][tx * 8];
            *(float4*)&b[4] = *(const float4*)&Bs[buf][kk][tx * 8 + 4];
            #pragma unroll
            for (int i = 0; i < 8; i++)
                #pragma unroll
                for (int j = 0; j < 8; j++)
                    acc[i][j] = fmaf(a[i], b[j], acc[i][j]);
        }
        __syncthreads();
    }

    float vmv[8];
    #pragma unroll
    for (int j = 0; j < 8; j++)
        vmv[j] = d_vm[n * MP + blockIdx.x * BN + tx * 8 + j];

    float local = 0.f;
    #pragma unroll
    for (int i = 0; i < 8; i++)
        #pragma unroll
        for (int j = 0; j < 8; j++)
            local += vmv[j] * fmaxf(acc[i][j] - 0.2f, 0.f);

    #pragma unroll
    for (int o = 16; o > 0; o >>= 1)
        local += __shfl_down_sync(0xffffffffu, local, o);

    __shared__ float wsum[8];
    if ((tid & 31) == 0) wsum[tid >> 5] = local;
    __syncthreads();
    if (tid == 0) {
        float t = 0.f;
        #pragma unroll
        for (int w = 0; w < 8; w++) t += wsum[w];
        d_partA[(blockIdx.z * GB + blockIdx.y) * GB + blockIdx.x] = t;
    }
#endif
}

// ---------------------------------------------------------------------------
// Positive-pair correction (coalesced bf16 dots on transposed arrays).
// ---------------------------------------------------------------------------
__device__ __forceinline__ float dot8(uint4 a, uint4 b) {
    const __nv_bfloat162* pa = (const __nv_bfloat162*)&a;
    const __nv_bfloat162* pb = (const __nv_bfloat162*)&b;
    float s = 0.f;
    #pragma unroll
    for (int k = 0; k < 4; k++) {
        float2 fa = __bfloat1622float2(pa[k]);
        float2 fb = __bfloat1622float2(pb[k]);
        s += fa.x * fb.x + fa.y * fb.y;
    }
    return s;
}

__global__ void pos_kernel(const float* __restrict__ homo) {
    int warp = threadIdx.x >> 5;
    int lane = threadIdx.x & 31;
    int item = blockIdx.x * 8 + warp;   // 0 .. 14399
    float contrib = 0.f;

    if (item < NB * M) {
        int n  = item / M;
        int ij = item % M;
        int i  = ij / WR, j = ij % WR;
        float x = j * 8 + 4.f, y = i * 8 + 4.f;
        const float* Hm = homo + n * 9;
        float wxh = Hm[0] * x + Hm[1] * y + Hm[2];
        float wyh = Hm[3] * x + Hm[4] * y + Hm[5];
        float wzh = Hm[6] * x + Hm[7] * y + Hm[8];
        float wx = wxh / wzh, wy = wyh / wzh;
        float vmv = d_vm[n * MP + ij];

        const uint4 bvec = ((const uint4*)(d_D2t + ((size_t)n * MP + ij) * C))[lane];

        int hs = (int)floorf((wy - 11.5f) * 0.125f);
        int ws = (int)floorf((wx - 11.5f) * 0.125f);
        for (int hh = hs; hh < hs + 4; hh++) {
            if (hh < 0 || hh >= HR) continue;
            float dy = hh * 8 + 4.f - wy;
            for (int wc = ws; wc < ws + 4; wc++) {
                if (wc < 0 || wc >= WR) continue;
                float dx = wc * 8 + 4.f - wx;
                if (dx * dx + dy * dy <= 56.25f) {   // dist <= 7.5
                    const uint4 avec =
                        ((const uint4*)(d_D1t + ((size_t)n * MP + hh * WR + wc) * C))[lane];
                    float dt = dot8(avec, bvec);
                    #pragma unroll
                    for (int o = 16; o > 0; o >>= 1)
                        dt += __shfl_down_sync(0xffffffffu, dt, o);
                    dt = __shfl_sync(0xffffffffu, dt, 0);
                    if (lane == 0)
                        contrib += vmv * (fmaxf(1.f - dt, 0.f) - fmaxf(dt - 0.2f, 0.f));
                }
            }
        }
    }

    __shared__ float wsh[8];
    if (lane == 0) wsh[warp] = contrib;
    __syncthreads();
    if (threadIdx.x == 0) {
        float t = 0.f;
        #pragma unroll
        for (int w = 0; w < 8; w++) t += wsh[w];
        d_partB[blockIdx.x] = t;
    }
}

// ---------------------------------------------------------------------------
// Final deterministic reduction. partA bound matches the active GEMM path.
// ---------------------------------------------------------------------------
__global__ void final_kernel(float* __restrict__ out) {
    __shared__ float sh[256];
    int tid = threadIdx.x;

#if HAS_TC
    const int NPA = NB * GB;        // 116 strip partials
#else
    const int NPA = GB * GB * NB;   // 3364 tile partials
#endif

    float s = 0.f;
    for (int k = tid; k < NPA; k += 256) s += d_partA[k];
    for (int k = tid; k < NPOSB; k += 256) s += d_partB[k];
    float v = 0.f;
    for (int k = tid; k < NB * MP; k += 256) v += d_vm[k];  // pads are 0

    sh[tid] = s;
    __syncthreads();
    for (int o = 128; o > 0; o >>= 1) {
        if (tid < o) sh[tid] += sh[tid + o];
        __syncthreads();
    }
    float total = sh[0];
    __syncthreads();

    sh[tid] = v;
    __syncthreads();
    for (int o = 128; o > 0; o >>= 1) {
        if (tid < o) sh[tid] += sh[tid + o];
        __syncthreads();
    }
    if (tid == 0)
        out[0] = total / (3600.f * sh[0]);   // LOSS_LAMBDA = 1
}

// ---------------------------------------------------------------------------
extern "C" void kernel_launch(void* const* d_in, const int* in_sizes, int n_in,
                              void* d_out, int out_size) {
    const float* desc1 = nullptr;
    const float* desc2 = nullptr;
    const float* homo  = nullptr;
    const float* vis   = nullptr;
    for (int k = 0; k < n_in; k++) {
        if (in_sizes[k] == NB * C * M) {
            if (!desc1) desc1 = (const float*)d_in[k];
            else if (!desc2) desc2 = (const float*)d_in[k];
        } else if (in_sizes[k] == NB * 9) {
            homo = (const float*)d_in[k];
        } else if (in_sizes[k] == NB * HH * WW) {
            vis = (const float*)d_in[k];
        }
    }

    // Idempotent, capture-safe.
    cudaFuncSetAttribute(gemm_tc_kernel,
                         cudaFuncAttributeMaxDynamicSharedMemorySize, 197632);

    transpose_kernel<<<dim3(116, 8, NB), dim3(32, 8)>>>(desc1, desc2);
    vm_kernel<<<(NB * MP + 255) / 256, 256>>>(vis);
    gemm_tc_kernel<<<dim3(GB, 1, NB), 288, 197632>>>();             // active on "a"
    gemm_simt_kernel<<<dim3(GB, GB, NB), 256>>>();                  // active otherwise
    pos_kernel<<<NPOSB, 256>>>(homo);
    final_kernel<<<1, 256>>>((float*)d_out);
}